// round 5
// baseline (speedup 1.0000x reference)
#include <cuda_runtime.h>
#include <cuda_bf16.h>
#include <math.h>
#include <stdint.h>

#define NQ 1024   // nodes
#define TT 1024   // tasks
#define DM 128
#define NH 4
#define HD 32
#define CH 256    // W1 out / W2 in
#define KO 128    // W2 out

// ---------------- scratch (static device memory; no allocs) ----------------
__device__ float g_qkv[NQ * 384];
__device__ float g_t1[TT * CH];
__device__ float g_scores[NH * NQ * NQ];   // 16 MB
__device__ float g_ctx[NQ * DM];
__device__ float g_att[NQ * DM];
__device__ float g_n1[NQ * CH];
__device__ __nv_bfloat16 g_n1bf[NQ * CH];
__device__ __nv_bfloat16 g_W2bf[KO * CH];

// ---------------- generic fp32 GEMM: C = alpha * A @ op(B) + bias ----------
// A[M,K] lda. transB=1: B[N,K] ldb (C=A@B^T). transB=0: B[K,N] ldb.
__global__ __launch_bounds__(256) void gemm_f32(
    const float* __restrict__ A, int lda,
    const float* __restrict__ B, int ldb, int transB,
    const float* __restrict__ bias, float alpha,
    float* __restrict__ C, int ldc, int M, int N, int K)
{
    __shared__ float As[16][68];
    __shared__ float Bs[16][68];
    int tid = threadIdx.x;
    int tx = tid & 15, ty = tid >> 4;
    int m0 = blockIdx.y * 64, n0 = blockIdx.x * 64;

    float acc[4][4];
#pragma unroll
    for (int i = 0; i < 4; i++)
#pragma unroll
        for (int j = 0; j < 4; j++) acc[i][j] = 0.f;

    for (int k0 = 0; k0 < K; k0 += 16) {
        // load A tile: idx -> k = idx&15, m = idx>>4 (coalesced along k)
#pragma unroll
        for (int it = 0; it < 4; it++) {
            int idx = tid + it * 256;
            int k = idx & 15, m = idx >> 4;
            float v = 0.f;
            if (m0 + m < M && k0 + k < K) v = A[(size_t)(m0 + m) * lda + k0 + k];
            As[k][m] = v;
        }
        // load B tile
        if (transB) {
#pragma unroll
            for (int it = 0; it < 4; it++) {
                int idx = tid + it * 256;
                int k = idx & 15, n = idx >> 4;
                float v = 0.f;
                if (n0 + n < N && k0 + k < K) v = B[(size_t)(n0 + n) * ldb + k0 + k];
                Bs[k][n] = v;
            }
        } else {
#pragma unroll
            for (int it = 0; it < 4; it++) {
                int idx = tid + it * 256;
                int n = idx & 63, k = idx >> 6;
                float v = 0.f;
                if (k0 + k < K && n0 + n < N) v = B[(size_t)(k0 + k) * ldb + n0 + n];
                Bs[k][n] = v;
            }
        }
        __syncthreads();
#pragma unroll
        for (int k = 0; k < 16; k++) {
            float4 a = *(const float4*)&As[k][ty * 4];
            float4 b = *(const float4*)&Bs[k][tx * 4];
            float av[4] = {a.x, a.y, a.z, a.w};
            float bv[4] = {b.x, b.y, b.z, b.w};
#pragma unroll
            for (int i = 0; i < 4; i++)
#pragma unroll
                for (int j = 0; j < 4; j++) acc[i][j] = fmaf(av[i], bv[j], acc[i][j]);
        }
        __syncthreads();
    }

#pragma unroll
    for (int i = 0; i < 4; i++) {
        int m = m0 + ty * 4 + i;
        if (m >= M) continue;
#pragma unroll
        for (int j = 0; j < 4; j++) {
            int n = n0 + tx * 4 + j;
            if (n >= N) continue;
            float v = alpha * acc[i][j];
            if (bias) v += bias[n];
            C[(size_t)m * ldc + n] = v;
        }
    }
}

// ---------------- softmax over rows of g_scores (4096 rows x 1024) ---------
__global__ __launch_bounds__(256) void softmax_rows()
{
    int row = blockIdx.x;
    float* p = g_scores + (size_t)row * 1024;
    int tid = threadIdx.x;
    __shared__ float red[8];
    __shared__ float red2[8];

    float v[4];
    float mx = -1e30f;
#pragma unroll
    for (int i = 0; i < 4; i++) { v[i] = p[tid + i * 256]; mx = fmaxf(mx, v[i]); }
#pragma unroll
    for (int o = 16; o; o >>= 1) mx = fmaxf(mx, __shfl_xor_sync(0xffffffffu, mx, o));
    if ((tid & 31) == 0) red[tid >> 5] = mx;
    __syncthreads();
    float m2 = red[0];
#pragma unroll
    for (int w = 1; w < 8; w++) m2 = fmaxf(m2, red[w]);

    float s = 0.f;
#pragma unroll
    for (int i = 0; i < 4; i++) { v[i] = expf(v[i] - m2); s += v[i]; }
#pragma unroll
    for (int o = 16; o; o >>= 1) s += __shfl_xor_sync(0xffffffffu, s, o);
    if ((tid & 31) == 0) red2[tid >> 5] = s;
    __syncthreads();
    float tot = 0.f;
#pragma unroll
    for (int w = 0; w < 8; w++) tot += red2[w];
    float inv = 1.f / tot;
#pragma unroll
    for (int i = 0; i < 4; i++) p[tid + i * 256] = v[i] * inv;
}

// ---------------- attn_w = mean over heads -> out segment -----------------
__global__ __launch_bounds__(256) void attn_mean(float* __restrict__ out)
{
    int idx = blockIdx.x * 256 + threadIdx.x;
    float s = g_scores[idx] + g_scores[idx + 1048576] +
              g_scores[idx + 2097152] + g_scores[idx + 3145728];
    out[idx] = 0.25f * s;
}

// ---------------- convert n1 and W2 to bf16 -------------------------------
__global__ __launch_bounds__(256) void convert_bf(const float* __restrict__ W2)
{
    int idx = blockIdx.x * 256 + threadIdx.x;
    if (idx < NQ * CH) g_n1bf[idx] = __float2bfloat16(g_n1[idx]);
    if (idx < KO * CH) g_W2bf[idx] = __float2bfloat16(W2[idx]);
}

// ---------------- coordination head ---------------------------------------
__global__ __launch_bounds__(256) void coord_kernel(
    const float* __restrict__ Wc1, const float* __restrict__ bc1,
    const float* __restrict__ Wc2, const float* __restrict__ bc2,
    float* __restrict__ out)
{
    __shared__ float ps[256];
    __shared__ float gs[128];
    __shared__ float h[256];
    int tid = threadIdx.x;
    int d = tid & 127, half = tid >> 7;
    float s = 0.f;
    for (int r = half * 512; r < half * 512 + 512; r++) s += g_att[r * 128 + d];
    ps[tid] = s;
    __syncthreads();
    if (tid < 128) gs[tid] = (ps[tid] + ps[tid + 128]) * (1.f / 1024.f);
    __syncthreads();
    float hv = bc1[tid];
    for (int c = 0; c < 128; c++) hv = fmaf(gs[c], Wc1[tid * 128 + c], hv);
    h[tid] = fmaxf(hv, 0.f);
    __syncthreads();
    if (tid < 32) {
        float z = bc2[tid];
        for (int c = 0; c < 256; c++) z = fmaf(h[c], Wc2[tid * 256 + c], z);
        out[tid] = z;
    }
}

// ---------------- fused pairwise MLP (the 34.4 GMAC kernel) ----------------
// CTA: 8 tasks x 16 nodes -> M=128 rows, N=128 (W2 out), K=256, bf16 HMMA.
#define SM_A 0
#define SM_B 67584
#define SM_T1 135168
#define SM_N1 143360
#define SM_W3 151552
#define SM_B2 152064
#define SM_ZP 152576
#define SMEM_TOTAL 153600
#define ROWSTRIDE_B 528  // bytes per smem row (264 bf16), 528 % 128 = 16 -> conflict-free ldmatrix

__device__ __forceinline__ void ldm_x4(uint32_t& r0, uint32_t& r1, uint32_t& r2, uint32_t& r3,
                                       uint32_t addr)
{
    asm volatile("ldmatrix.sync.aligned.m8n8.x4.shared.b16 {%0,%1,%2,%3}, [%4];"
                 : "=r"(r0), "=r"(r1), "=r"(r2), "=r"(r3)
                 : "r"(addr));
}

__device__ __forceinline__ void mma_bf16(float& c0, float& c1, float& c2, float& c3,
                                         uint32_t a0, uint32_t a1, uint32_t a2, uint32_t a3,
                                         uint32_t b0, uint32_t b1)
{
    asm volatile(
        "mma.sync.aligned.m16n8k16.row.col.f32.bf16.bf16.f32 "
        "{%0,%1,%2,%3}, {%4,%5,%6,%7}, {%8,%9}, {%0,%1,%2,%3};"
        : "+f"(c0), "+f"(c1), "+f"(c2), "+f"(c3)
        : "r"(a0), "r"(a1), "r"(a2), "r"(a3), "r"(b0), "r"(b1));
}

__global__ __launch_bounds__(256) void match_kernel(
    const float* __restrict__ W3, const float* __restrict__ b2v,
    const float* __restrict__ b3, float* __restrict__ out)
{
    extern __shared__ char sm[];
    __nv_bfloat16* sA = (__nv_bfloat16*)(sm + SM_A);
    __nv_bfloat16* sB = (__nv_bfloat16*)(sm + SM_B);
    float* t1s = (float*)(sm + SM_T1);
    float* sW3 = (float*)(sm + SM_W3);
    float* sb2 = (float*)(sm + SM_B2);
    float* zpart = (float*)(sm + SM_ZP);

    int tid = threadIdx.x;
    int n0 = blockIdx.x * 16, t0 = blockIdx.y * 8;

    // stage t1 (8 rows, fp32) and n1 (16 rows, bf16)
    const float* t1g = g_t1 + t0 * 256;
    for (int i = tid; i < 2048; i += 256) t1s[i] = t1g[i];
    const uint32_t* n1src = (const uint32_t*)(g_n1bf + n0 * 256);
    uint32_t* n1d = (uint32_t*)(sm + SM_N1);
    for (int i = tid; i < 2048; i += 256) n1d[i] = n1src[i];
    if (tid < 128) { sW3[tid] = W3[tid]; sb2[tid] = b2v[tid]; }

    // stage B = W2 bf16 (128 x 256 bf16 = 128 rows x 32 uint4, padded rows)
    const uint4* bsrc = (const uint4*)g_W2bf;
    for (int i = tid; i < 4096; i += 256) {
        int r = i >> 5, q = i & 31;
        *(uint4*)((char*)sB + r * ROWSTRIDE_B + q * 16) = bsrc[i];
    }
    __syncthreads();

    // build A[r][c] = relu(t1[t0 + r/16][c] + n1[n0 + r%16][c]) as bf16
    const __nv_bfloat16* n1s = (const __nv_bfloat16*)(sm + SM_N1);
    for (int i = tid; i < 16384; i += 256) {
        int r = i >> 7, p = i & 127;
        int tl = r >> 4, nl = r & 15;
        uint32_t nv = ((const uint32_t*)n1s)[nl * 128 + p];
        __nv_bfloat162 nb = *(__nv_bfloat162*)&nv;
        float x0 = t1s[tl * 256 + 2 * p]     + __bfloat162float(nb.x);
        float x1 = t1s[tl * 256 + 2 * p + 1] + __bfloat162float(nb.y);
        __nv_bfloat162 o = __floats2bfloat162_rn(fmaxf(x0, 0.f), fmaxf(x1, 0.f));
        *(uint32_t*)((char*)sA + r * ROWSTRIDE_B + p * 4) = *(uint32_t*)&o;
    }
    __syncthreads();

    int lane = tid & 31, wid = tid >> 5;
    int wm = wid >> 1, wn = wid & 1;  // warp tile: M 32 (wm*32), N 64 (wn*64)

    float c[2][8][4];
#pragma unroll
    for (int mt = 0; mt < 2; mt++)
#pragma unroll
        for (int nt = 0; nt < 8; nt++)
#pragma unroll
            for (int j = 0; j < 4; j++) c[mt][nt][j] = 0.f;

    uint32_t aSm = (uint32_t)__cvta_generic_to_shared(sA);
    uint32_t bSm = (uint32_t)__cvta_generic_to_shared(sB);

    // ldmatrix base addresses
    uint32_t aBase[2];
#pragma unroll
    for (int mt = 0; mt < 2; mt++) {
        int row = wm * 32 + mt * 16 + (lane & 15);
        int colb = ((lane >> 4) << 3) * 2;  // 0 or 16 bytes
        aBase[mt] = aSm + row * ROWSTRIDE_B + colb;
    }
    uint32_t bBase[4];
#pragma unroll
    for (int nt2 = 0; nt2 < 4; nt2++) {
        int nrow = wn * 64 + nt2 * 16 + ((lane >> 4) << 3) + (lane & 7);
        int kb = (((lane >> 3) & 1) << 3) * 2;  // 0 or 16 bytes
        bBase[nt2] = bSm + nrow * ROWSTRIDE_B + kb;
    }

#pragma unroll
    for (int kk = 0; kk < 16; kk++) {
        uint32_t a[2][4];
#pragma unroll
        for (int mt = 0; mt < 2; mt++)
            ldm_x4(a[mt][0], a[mt][1], a[mt][2], a[mt][3], aBase[mt] + kk * 32);
        uint32_t b[8][2];
#pragma unroll
        for (int nt2 = 0; nt2 < 4; nt2++) {
            uint32_t r0, r1, r2, r3;
            ldm_x4(r0, r1, r2, r3, bBase[nt2] + kk * 32);
            b[2 * nt2][0] = r0; b[2 * nt2][1] = r1;
            b[2 * nt2 + 1][0] = r2; b[2 * nt2 + 1][1] = r3;
        }
#pragma unroll
        for (int mt = 0; mt < 2; mt++)
#pragma unroll
            for (int nt = 0; nt < 8; nt++)
                mma_bf16(c[mt][nt][0], c[mt][nt][1], c[mt][nt][2], c[mt][nt][3],
                         a[mt][0], a[mt][1], a[mt][2], a[mt][3],
                         b[nt][0], b[nt][1]);
    }

    // epilogue: z[r] = sum_k relu(h2[r][k] + b2[k]) * W3[k]
    int g = lane >> 2, q = lane & 3;
#pragma unroll
    for (int mt = 0; mt < 2; mt++) {
        float p0 = 0.f, p1 = 0.f;
#pragma unroll
        for (int nt = 0; nt < 8; nt++) {
            int col = wn * 64 + nt * 8 + q * 2;
            float w0 = sW3[col], w1 = sW3[col + 1];
            float bb0 = sb2[col], bb1 = sb2[col + 1];
            p0 += fmaxf(c[mt][nt][0] + bb0, 0.f) * w0 + fmaxf(c[mt][nt][1] + bb1, 0.f) * w1;
            p1 += fmaxf(c[mt][nt][2] + bb0, 0.f) * w0 + fmaxf(c[mt][nt][3] + bb1, 0.f) * w1;
        }
        p0 += __shfl_xor_sync(0xffffffffu, p0, 1);
        p0 += __shfl_xor_sync(0xffffffffu, p0, 2);
        p1 += __shfl_xor_sync(0xffffffffu, p1, 1);
        p1 += __shfl_xor_sync(0xffffffffu, p1, 2);
        if (q == 0) {
            int rA = wm * 32 + mt * 16 + g;
            zpart[rA * 2 + wn] = p0;
            zpart[(rA + 8) * 2 + wn] = p1;
        }
    }
    __syncthreads();
    if (tid < 128) {
        float z = zpart[tid * 2] + zpart[tid * 2 + 1] + b3[0];
        float s = 1.f / (1.f + expf(-z));
        int t = t0 + (tid >> 4), n = n0 + (tid & 15);
        out[(size_t)t * 1024 + n] = s;
    }
}

// ---------------- launch ---------------------------------------------------
extern "C" void kernel_launch(void* const* d_in, const int* in_sizes, int n_in,
                              void* d_out, int out_size)
{
    const float* node = (const float*)d_in[0];
    const float* task = (const float*)d_in[1];
    const float* ipw  = (const float*)d_in[2];
    const float* ipb  = (const float*)d_in[3];
    const float* outw = (const float*)d_in[4];
    const float* outb = (const float*)d_in[5];
    const float* W1   = (const float*)d_in[6];
    const float* b1   = (const float*)d_in[7];
    const float* W2   = (const float*)d_in[8];
    const float* b2   = (const float*)d_in[9];
    const float* W3   = (const float*)d_in[10];
    const float* b3   = (const float*)d_in[11];
    const float* Wc1  = (const float*)d_in[12];
    const float* bc1  = (const float*)d_in[13];
    const float* Wc2  = (const float*)d_in[14];
    const float* bc2  = (const float*)d_in[15];
    float* out = (float*)d_out;

    float *qkv, *t1, *scores, *ctx, *att, *n1;
    cudaGetSymbolAddress((void**)&qkv, g_qkv);
    cudaGetSymbolAddress((void**)&t1, g_t1);
    cudaGetSymbolAddress((void**)&scores, g_scores);
    cudaGetSymbolAddress((void**)&ctx, g_ctx);
    cudaGetSymbolAddress((void**)&att, g_att);
    cudaGetSymbolAddress((void**)&n1, g_n1);

    // QKV: [1024,128] @ in_proj_w[384,128]^T + b -> g_qkv[1024,384]
    gemm_f32<<<dim3(6, 16), 256>>>(node, 128, ipw, 128, 1, ipb, 1.f, qkv, 384, 1024, 384, 128);
    // t1: task @ W1[:, :128]^T + b1 -> [1024,256]
    gemm_f32<<<dim3(4, 16), 256>>>(task, 128, W1, 256, 1, b1, 1.f, t1, 256, 1024, 256, 128);
    // attention scores per head: q_h @ k_h^T / sqrt(32)
    for (int h = 0; h < 4; h++)
        gemm_f32<<<dim3(16, 16), 256>>>(qkv + h * 32, 384, qkv + 128 + h * 32, 384, 1,
                                        nullptr, 0.17677669529663687f,
                                        scores + (size_t)h * 1048576, 1024, 1024, 1024, 32);
    softmax_rows<<<4096, 256>>>();
    attn_mean<<<4096, 256>>>(out + 1048608);
    // ctx per head: P @ v_h -> g_ctx[:, h*32:(h+1)*32]
    for (int h = 0; h < 4; h++)
        gemm_f32<<<dim3(1, 16), 256>>>(scores + (size_t)h * 1048576, 1024,
                                       qkv + 256 + h * 32, 384, 0, nullptr, 1.f,
                                       ctx + h * 32, 128, 1024, 32, 1024);
    // attended = ctx @ out_w^T + out_b
    gemm_f32<<<dim3(2, 16), 256>>>(ctx, 128, outw, 128, 1, outb, 1.f, att, 128, 1024, 128, 128);
    // n1 = attended @ W1[:, 128:]^T
    gemm_f32<<<dim3(4, 16), 256>>>(att, 128, W1 + 128, 256, 1, nullptr, 1.f, n1, 256, 1024, 256, 128);
    // bf16 conversion of n1 and W2
    convert_bf<<<1024, 256>>>(W2);
    // big fused pairwise MLP
    cudaFuncSetAttribute(match_kernel, cudaFuncAttributeMaxDynamicSharedMemorySize, SMEM_TOTAL);
    match_kernel<<<dim3(64, 128), 256, SMEM_TOTAL>>>(W3, b2, b3, out);
    // coordination head
    coord_kernel<<<1, 256>>>(Wc1, bc1, Wc2, bc2, out + 1048576);
}

// round 7
// speedup vs baseline: 1.6480x; 1.6480x over previous
#include <cuda_runtime.h>
#include <cuda_bf16.h>
#include <math.h>
#include <stdint.h>

#define NQ 1024
#define TT 1024
#define DM 128
#define CH 256
#define KO 128

// ---------------- scratch (static device memory; no allocs) ----------------
__device__ float g_qkv[NQ * 384];
__device__ float g_t1[TT * CH];
__device__ float g_scores[4 * NQ * NQ];
__device__ float g_ctx[NQ * DM];
__device__ float g_att[NQ * DM];
__device__ float g_n1[NQ * CH];
__device__ __nv_bfloat16 g_n1bf[NQ * CH];
__device__ __nv_bfloat16 g_W2bf[KO * CH];

// ---------------- batched fp32 GEMM with optional split-K -------------------
// z -> (h = z % nz, kc = z / nz). C = alpha*A@op(B) (+bias). kchunks>1: atomicAdd.
__global__ __launch_bounds__(256) void gemm_f32b(
    const float* __restrict__ A, int lda, int sAz,
    const float* __restrict__ B, int ldb, int sBz, int transB,
    const float* __restrict__ bias, float alpha,
    float* __restrict__ C, int ldc, int sCz,
    int M, int N, int K, int nz, int kchunks)
{
    __shared__ float As[16][68];
    __shared__ float Bs[16][68];
    int tid = threadIdx.x;
    int tx = tid & 15, ty = tid >> 4;
    int m0 = blockIdx.y * 64, n0 = blockIdx.x * 64;
    int h = blockIdx.z % nz, kc = blockIdx.z / nz;
    A += (size_t)h * sAz; B += (size_t)h * sBz; C += (size_t)h * sCz;
    int KC = K / kchunks;
    int kLo = kc * KC, kHi = kLo + KC;

    float acc[4][4];
#pragma unroll
    for (int i = 0; i < 4; i++)
#pragma unroll
        for (int j = 0; j < 4; j++) acc[i][j] = 0.f;

    for (int k0 = kLo; k0 < kHi; k0 += 16) {
#pragma unroll
        for (int it = 0; it < 4; it++) {
            int idx = tid + it * 256;
            int k = idx & 15, m = idx >> 4;
            float v = 0.f;
            if (m0 + m < M && k0 + k < K) v = A[(size_t)(m0 + m) * lda + k0 + k];
            As[k][m] = v;
        }
        if (transB) {
#pragma unroll
            for (int it = 0; it < 4; it++) {
                int idx = tid + it * 256;
                int k = idx & 15, n = idx >> 4;
                float v = 0.f;
                if (n0 + n < N && k0 + k < K) v = B[(size_t)(n0 + n) * ldb + k0 + k];
                Bs[k][n] = v;
            }
        } else {
#pragma unroll
            for (int it = 0; it < 4; it++) {
                int idx = tid + it * 256;
                int n = idx & 63, k = idx >> 6;
                float v = 0.f;
                if (k0 + k < K && n0 + n < N) v = B[(size_t)(k0 + k) * ldb + n0 + n];
                Bs[k][n] = v;
            }
        }
        __syncthreads();
#pragma unroll
        for (int k = 0; k < 16; k++) {
            float4 a = *(const float4*)&As[k][ty * 4];
            float4 b = *(const float4*)&Bs[k][tx * 4];
            float av[4] = {a.x, a.y, a.z, a.w};
            float bv[4] = {b.x, b.y, b.z, b.w};
#pragma unroll
            for (int i = 0; i < 4; i++)
#pragma unroll
                for (int j = 0; j < 4; j++) acc[i][j] = fmaf(av[i], bv[j], acc[i][j]);
        }
        __syncthreads();
    }

#pragma unroll
    for (int i = 0; i < 4; i++) {
        int m = m0 + ty * 4 + i;
        if (m >= M) continue;
#pragma unroll
        for (int j = 0; j < 4; j++) {
            int n = n0 + tx * 4 + j;
            if (n >= N) continue;
            float v = alpha * acc[i][j];
            if (bias) v += bias[n];
            if (kchunks == 1) C[(size_t)m * ldc + n] = v;
            else atomicAdd(&C[(size_t)m * ldc + n], v);
        }
    }
}

__global__ __launch_bounds__(256) void zero_ctx()
{
    ((float4*)g_ctx)[blockIdx.x * 256 + threadIdx.x] = make_float4(0.f, 0.f, 0.f, 0.f);
}

// ---------------- softmax over rows of g_scores (4096 rows x 1024) ---------
__global__ __launch_bounds__(256) void softmax_rows()
{
    int row = blockIdx.x;
    float* p = g_scores + (size_t)row * 1024;
    int tid = threadIdx.x;
    __shared__ float red[8];
    __shared__ float red2[8];

    float v[4];
    float mx = -1e30f;
#pragma unroll
    for (int i = 0; i < 4; i++) { v[i] = p[tid + i * 256]; mx = fmaxf(mx, v[i]); }
#pragma unroll
    for (int o = 16; o; o >>= 1) mx = fmaxf(mx, __shfl_xor_sync(0xffffffffu, mx, o));
    if ((tid & 31) == 0) red[tid >> 5] = mx;
    __syncthreads();
    float m2 = red[0];
#pragma unroll
    for (int w = 1; w < 8; w++) m2 = fmaxf(m2, red[w]);

    float s = 0.f;
#pragma unroll
    for (int i = 0; i < 4; i++) { v[i] = expf(v[i] - m2); s += v[i]; }
#pragma unroll
    for (int o = 16; o; o >>= 1) s += __shfl_xor_sync(0xffffffffu, s, o);
    if ((tid & 31) == 0) red2[tid >> 5] = s;
    __syncthreads();
    float tot = 0.f;
#pragma unroll
    for (int w = 0; w < 8; w++) tot += red2[w];
    float inv = 1.f / tot;
#pragma unroll
    for (int i = 0; i < 4; i++) p[tid + i * 256] = v[i] * inv;
}

__global__ __launch_bounds__(256) void attn_mean(float* __restrict__ out)
{
    int idx = blockIdx.x * 256 + threadIdx.x;
    float s = g_scores[idx] + g_scores[idx + 1048576] +
              g_scores[idx + 2097152] + g_scores[idx + 3145728];
    out[idx] = 0.25f * s;
}

__global__ __launch_bounds__(256) void convert_bf(const float* __restrict__ W2)
{
    int idx = blockIdx.x * 256 + threadIdx.x;
    if (idx < NQ * CH) g_n1bf[idx] = __float2bfloat16(g_n1[idx]);
    if (idx < KO * CH) g_W2bf[idx] = __float2bfloat16(W2[idx]);
}

__global__ __launch_bounds__(256) void coord_kernel(
    const float* __restrict__ Wc1, const float* __restrict__ bc1,
    const float* __restrict__ Wc2, const float* __restrict__ bc2,
    float* __restrict__ out)
{
    __shared__ float ps[256];
    __shared__ float gs[128];
    __shared__ float h[256];
    int tid = threadIdx.x;
    int d = tid & 127, half = tid >> 7;
    float s = 0.f;
    for (int r = half * 512; r < half * 512 + 512; r++) s += g_att[r * 128 + d];
    ps[tid] = s;
    __syncthreads();
    if (tid < 128) gs[tid] = (ps[tid] + ps[tid + 128]) * (1.f / 1024.f);
    __syncthreads();
    float hv = bc1[tid];
    for (int c = 0; c < 128; c++) hv = fmaf(gs[c], Wc1[tid * 128 + c], hv);
    h[tid] = fmaxf(hv, 0.f);
    __syncthreads();
    if (tid < 32) {
        float z = bc2[tid];
        for (int c = 0; c < 256; c++) z = fmaf(h[c], Wc2[tid * 256 + c], z);
        out[tid] = z;
    }
}

// ============== persistent pairwise MLP (34.4 GMAC, bf16 mma.sync) ==========
// Grid = 152 persistent CTAs, 54 tiles each. W2 staged to SMEM once per CTA.
// Per tile: A[128,256] bf16 = relu(t1+n1), HMMA M128 N128 K256, fused epilogue.

#define GRID_MATCH 152
#define NTILES 8192

#define SM_A 0
#define SM_B 67584
#define SM_T1 135168
#define SM_N1 143360
#define SM_W3 151552
#define SM_B2 152064
#define SM_ZP 152576
#define SMEM_TOTAL 153600
#define ROWSTRIDE_B 528  // bytes per smem row (264 bf16); 132 words % 32 banks = 4 -> conflict-free ldmatrix

__device__ __forceinline__ void ldm_x4(uint32_t& r0, uint32_t& r1, uint32_t& r2, uint32_t& r3,
                                       uint32_t addr)
{
    asm volatile("ldmatrix.sync.aligned.m8n8.x4.shared.b16 {%0,%1,%2,%3}, [%4];"
                 : "=r"(r0), "=r"(r1), "=r"(r2), "=r"(r3)
                 : "r"(addr));
}

__device__ __forceinline__ void mma_bf16(float& c0, float& c1, float& c2, float& c3,
                                         uint32_t a0, uint32_t a1, uint32_t a2, uint32_t a3,
                                         uint32_t b0, uint32_t b1)
{
    asm volatile(
        "mma.sync.aligned.m16n8k16.row.col.f32.bf16.bf16.f32 "
        "{%0,%1,%2,%3}, {%4,%5,%6,%7}, {%8,%9}, {%0,%1,%2,%3};"
        : "+f"(c0), "+f"(c1), "+f"(c2), "+f"(c3)
        : "r"(a0), "r"(a1), "r"(a2), "r"(a3), "r"(b0), "r"(b1));
}

__device__ __forceinline__ uint32_t rp2(float a, float b, uint32_t nv)
{
    __nv_bfloat162 n = *reinterpret_cast<const __nv_bfloat162*>(&nv);
    float x0 = a + __bfloat162float(n.x);
    float x1 = b + __bfloat162float(n.y);
    __nv_bfloat162 o = __floats2bfloat162_rn(fmaxf(x0, 0.f), fmaxf(x1, 0.f));
    return *reinterpret_cast<uint32_t*>(&o);
}

__global__ __launch_bounds__(256, 1) void match_kernel(
    const float* __restrict__ W3, const float* __restrict__ b2v,
    const float* __restrict__ b3, float* __restrict__ out)
{
    extern __shared__ char sm[];
    float* t1s = (float*)(sm + SM_T1);
    float* sW3 = (float*)(sm + SM_W3);
    float* sb2 = (float*)(sm + SM_B2);
    float* zpart = (float*)(sm + SM_ZP);

    int tid = threadIdx.x;
    int lane = tid & 31, wid = tid >> 5;
    int wm = wid >> 1, wn = wid & 1;  // warp tile: M32 (wm), N64 (wn)

    // ---- one-time staging: W2, W3, b2 ----
    {
        const uint4* bsrc = (const uint4*)g_W2bf;
#pragma unroll
        for (int j = 0; j < 16; j++) {
            int i = tid + j * 256;
            int r = i >> 5, q = i & 31;
            *(uint4*)(sm + SM_B + r * ROWSTRIDE_B + q * 16) = bsrc[i];
        }
        if (tid < 128) { sW3[tid] = W3[tid]; sb2[tid] = b2v[tid]; }
    }
    float b3v = b3[0];

    uint32_t aSm = (uint32_t)__cvta_generic_to_shared(sm + SM_A);
    uint32_t bSm = (uint32_t)__cvta_generic_to_shared(sm + SM_B);

    // ldmatrix base addresses (fixed for all tiles)
    uint32_t aBase[2];
#pragma unroll
    for (int mt = 0; mt < 2; mt++) {
        int row = wm * 32 + mt * 16 + (lane & 15);
        int colb = ((lane >> 4) << 3) * 2;
        aBase[mt] = aSm + row * ROWSTRIDE_B + colb;
    }
    uint32_t bBase[4];
#pragma unroll
    for (int nt2 = 0; nt2 < 4; nt2++) {
        int nrow = wn * 64 + nt2 * 16 + ((lane >> 4) << 3) + (lane & 7);
        int kb = (((lane >> 3) & 1) << 3) * 2;
        bBase[nt2] = bSm + nrow * ROWSTRIDE_B + kb;
    }
    __syncthreads();

    for (int tile = blockIdx.x; tile < NTILES; tile += GRID_MATCH) {
        int n0 = (tile & 63) * 16, t0 = (tile >> 6) * 8;

        // ---- stage t1 (8x256 f32) + n1 (16x256 bf16) ----
        {
            const float4* ts = (const float4*)(g_t1 + (size_t)t0 * 256);
            float4* td = (float4*)t1s;
            const uint4* ns = (const uint4*)(g_n1bf + (size_t)n0 * 256);
            uint4* nd = (uint4*)(sm + SM_N1);
            td[tid] = ts[tid];
            td[tid + 256] = ts[tid + 256];
            nd[tid] = ns[tid];
            nd[tid + 256] = ns[tid + 256];
        }
        __syncthreads();

        // ---- build A[r][c] = relu(t1[r/16][c] + n1[r%16][c]) bf16 ----
        {
            const float4* t1f4 = (const float4*)t1s;
            const uint4* n1u4 = (const uint4*)(sm + SM_N1);
#pragma unroll
            for (int j = 0; j < 16; j++) {
                int idx = tid + j * 256;
                int r = idx >> 5, q = idx & 31;
                int tl = r >> 4, nl = r & 15;
                float4 ta = t1f4[tl * 64 + q * 2];
                float4 tb = t1f4[tl * 64 + q * 2 + 1];
                uint4 nv = n1u4[nl * 32 + q];
                uint4 o;
                o.x = rp2(ta.x, ta.y, nv.x);
                o.y = rp2(ta.z, ta.w, nv.y);
                o.z = rp2(tb.x, tb.y, nv.z);
                o.w = rp2(tb.z, tb.w, nv.w);
                *(uint4*)(sm + SM_A + r * ROWSTRIDE_B + q * 16) = o;
            }
        }
        __syncthreads();

        // ---- HMMA mainloop ----
        float c[2][8][4];
#pragma unroll
        for (int mt = 0; mt < 2; mt++)
#pragma unroll
            for (int nt = 0; nt < 8; nt++)
#pragma unroll
                for (int j = 0; j < 4; j++) c[mt][nt][j] = 0.f;

#pragma unroll
        for (int kk = 0; kk < 16; kk++) {
            uint32_t a[2][4];
#pragma unroll
            for (int mt = 0; mt < 2; mt++)
                ldm_x4(a[mt][0], a[mt][1], a[mt][2], a[mt][3], aBase[mt] + kk * 32);
            uint32_t b[8][2];
#pragma unroll
            for (int nt2 = 0; nt2 < 4; nt2++) {
                uint32_t r0, r1, r2, r3;
                ldm_x4(r0, r1, r2, r3, bBase[nt2] + kk * 32);
                b[2 * nt2][0] = r0; b[2 * nt2][1] = r1;
                b[2 * nt2 + 1][0] = r2; b[2 * nt2 + 1][1] = r3;
            }
#pragma unroll
            for (int mt = 0; mt < 2; mt++)
#pragma unroll
                for (int nt = 0; nt < 8; nt++)
                    mma_bf16(c[mt][nt][0], c[mt][nt][1], c[mt][nt][2], c[mt][nt][3],
                             a[mt][0], a[mt][1], a[mt][2], a[mt][3],
                             b[nt][0], b[nt][1]);
        }

        // ---- epilogue: z[r] = sum_k relu(h2[r][k] + b2[k]) * W3[k] ----
        int g = lane >> 2, q = lane & 3;
#pragma unroll
        for (int mt = 0; mt < 2; mt++) {
            float p0 = 0.f, p1 = 0.f;
#pragma unroll
            for (int nt = 0; nt < 8; nt++) {
                int col = wn * 64 + nt * 8 + q * 2;
                float w0 = sW3[col], w1 = sW3[col + 1];
                float bb0 = sb2[col], bb1 = sb2[col + 1];
                p0 += fmaxf(c[mt][nt][0] + bb0, 0.f) * w0 + fmaxf(c[mt][nt][1] + bb1, 0.f) * w1;
                p1 += fmaxf(c[mt][nt][2] + bb0, 0.f) * w0 + fmaxf(c[mt][nt][3] + bb1, 0.f) * w1;
            }
            p0 += __shfl_xor_sync(0xffffffffu, p0, 1);
            p0 += __shfl_xor_sync(0xffffffffu, p0, 2);
            p1 += __shfl_xor_sync(0xffffffffu, p1, 1);
            p1 += __shfl_xor_sync(0xffffffffu, p1, 2);
            if (q == 0) {
                int rA = wm * 32 + mt * 16 + g;
                zpart[rA * 2 + wn] = p0;
                zpart[(rA + 8) * 2 + wn] = p1;
            }
        }
        __syncthreads();
        if (tid < 128) {
            float z = zpart[tid * 2] + zpart[tid * 2 + 1] + b3v;
            float s = 1.f / (1.f + expf(-z));
            int t = t0 + (tid >> 4), n = n0 + (tid & 15);
            out[(size_t)t * 1024 + n] = s;
        }
        __syncthreads();
    }
}

// ---------------- launch ---------------------------------------------------
extern "C" void kernel_launch(void* const* d_in, const int* in_sizes, int n_in,
                              void* d_out, int out_size)
{
    const float* node = (const float*)d_in[0];
    const float* task = (const float*)d_in[1];
    const float* ipw  = (const float*)d_in[2];
    const float* ipb  = (const float*)d_in[3];
    const float* outw = (const float*)d_in[4];
    const float* outb = (const float*)d_in[5];
    const float* W1   = (const float*)d_in[6];
    const float* b1   = (const float*)d_in[7];
    const float* W2   = (const float*)d_in[8];
    const float* b2   = (const float*)d_in[9];
    const float* W3   = (const float*)d_in[10];
    const float* b3   = (const float*)d_in[11];
    const float* Wc1  = (const float*)d_in[12];
    const float* bc1  = (const float*)d_in[13];
    const float* Wc2  = (const float*)d_in[14];
    const float* bc2  = (const float*)d_in[15];
    float* out = (float*)d_out;

    float *qkv, *t1, *scores, *ctx, *att, *n1;
    cudaGetSymbolAddress((void**)&qkv, g_qkv);
    cudaGetSymbolAddress((void**)&t1, g_t1);
    cudaGetSymbolAddress((void**)&scores, g_scores);
    cudaGetSymbolAddress((void**)&ctx, g_ctx);
    cudaGetSymbolAddress((void**)&att, g_att);
    cudaGetSymbolAddress((void**)&n1, g_n1);

    // QKV: node @ in_proj_w^T + b
    gemm_f32b<<<dim3(6, 16, 1), 256>>>(node, 128, 0, ipw, 128, 0, 1, ipb, 1.f,
                                       qkv, 384, 0, 1024, 384, 128, 1, 1);
    // t1 = task @ W1[:, :128]^T + b1
    gemm_f32b<<<dim3(4, 16, 1), 256>>>(task, 128, 0, W1, 256, 0, 1, b1, 1.f,
                                       t1, 256, 0, 1024, 256, 128, 1, 1);
    // scores: all 4 heads in one launch (z = head)
    gemm_f32b<<<dim3(16, 16, 4), 256>>>(qkv, 384, 32, qkv + 128, 384, 32, 1,
                                        nullptr, 0.17677669529663687f,
                                        scores, 1024, 1048576, 1024, 1024, 32, 4, 1);
    softmax_rows<<<4096, 256>>>();
    attn_mean<<<4096, 256>>>(out + 1048608);
    // ctx: 4 heads x split-K(4) with atomic accumulation
    zero_ctx<<<128, 256>>>();
    gemm_f32b<<<dim3(1, 16, 16), 256>>>(scores, 1024, 1048576, qkv + 256, 384, 32, 0,
                                        nullptr, 1.f, ctx, 128, 32,
                                        1024, 32, 1024, 4, 4);
    // attended = ctx @ out_w^T + out_b
    gemm_f32b<<<dim3(2, 16, 1), 256>>>(ctx, 128, 0, outw, 128, 0, 1, outb, 1.f,
                                       att, 128, 0, 1024, 128, 128, 1, 1);
    // n1 = attended @ W1[:, 128:]^T
    gemm_f32b<<<dim3(4, 16, 1), 256>>>(att, 128, 0, W1 + 128, 256, 0, 1, nullptr, 1.f,
                                       n1, 256, 0, 1024, 256, 128, 1, 1);
    convert_bf<<<1024, 256>>>(W2);
    // persistent bf16 HMMA pairwise MLP
    cudaFuncSetAttribute(match_kernel, cudaFuncAttributeMaxDynamicSharedMemorySize, SMEM_TOTAL);
    match_kernel<<<GRID_MATCH, 256, SMEM_TOTAL>>>(W3, b2, b3, out);
    // coordination head
    coord_kernel<<<1, 256>>>(Wc1, bc1, Wc2, bc2, out + 1048576);
}

// round 10
// speedup vs baseline: 2.5146x; 1.5259x over previous
#include <cuda_runtime.h>
#include <cuda_bf16.h>
#include <math.h>
#include <stdint.h>

#define NQ 1024
#define TT 1024
#define DM 128
#define CH 256
#define KO 128

// ---------------- scratch (static device memory; no allocs) ----------------
__device__ float g_qkv[NQ * 384];
__device__ float g_t1[TT * CH];
__device__ float g_scores[4 * NQ * NQ];
__device__ float g_ctx[NQ * DM];
__device__ float g_att[NQ * DM];
__device__ float g_n1[NQ * CH];
__device__ __nv_bfloat16 g_n1bf[NQ * CH];
__device__ __nv_bfloat16 g_W2bf[KO * CH];

// ---------------- batched fp32 GEMM with optional split-K -------------------
__global__ __launch_bounds__(256) void gemm_f32b(
    const float* __restrict__ A, int lda, int sAz,
    const float* __restrict__ B, int ldb, int sBz, int transB,
    const float* __restrict__ bias, float alpha,
    float* __restrict__ C, int ldc, int sCz,
    int M, int N, int K, int nz, int kchunks)
{
    __shared__ float As[16][68];
    __shared__ float Bs[16][68];
    int tid = threadIdx.x;
    int tx = tid & 15, ty = tid >> 4;
    int m0 = blockIdx.y * 64, n0 = blockIdx.x * 64;
    int h = blockIdx.z % nz, kc = blockIdx.z / nz;
    A += (size_t)h * sAz; B += (size_t)h * sBz; C += (size_t)h * sCz;
    int KC = K / kchunks;
    int kLo = kc * KC, kHi = kLo + KC;

    float acc[4][4];
#pragma unroll
    for (int i = 0; i < 4; i++)
#pragma unroll
        for (int j = 0; j < 4; j++) acc[i][j] = 0.f;

    for (int k0 = kLo; k0 < kHi; k0 += 16) {
#pragma unroll
        for (int it = 0; it < 4; it++) {
            int idx = tid + it * 256;
            int k = idx & 15, m = idx >> 4;
            float v = 0.f;
            if (m0 + m < M && k0 + k < K) v = A[(size_t)(m0 + m) * lda + k0 + k];
            As[k][m] = v;
        }
        if (transB) {
#pragma unroll
            for (int it = 0; it < 4; it++) {
                int idx = tid + it * 256;
                int k = idx & 15, n = idx >> 4;
                float v = 0.f;
                if (n0 + n < N && k0 + k < K) v = B[(size_t)(n0 + n) * ldb + k0 + k];
                Bs[k][n] = v;
            }
        } else {
#pragma unroll
            for (int it = 0; it < 4; it++) {
                int idx = tid + it * 256;
                int n = idx & 63, k = idx >> 6;
                float v = 0.f;
                if (k0 + k < K && n0 + n < N) v = B[(size_t)(k0 + k) * ldb + n0 + n];
                Bs[k][n] = v;
            }
        }
        __syncthreads();
#pragma unroll
        for (int k = 0; k < 16; k++) {
            float4 a = *(const float4*)&As[k][ty * 4];
            float4 b = *(const float4*)&Bs[k][tx * 4];
            float av[4] = {a.x, a.y, a.z, a.w};
            float bv[4] = {b.x, b.y, b.z, b.w};
#pragma unroll
            for (int i = 0; i < 4; i++)
#pragma unroll
                for (int j = 0; j < 4; j++) acc[i][j] = fmaf(av[i], bv[j], acc[i][j]);
        }
        __syncthreads();
    }

#pragma unroll
    for (int i = 0; i < 4; i++) {
        int m = m0 + ty * 4 + i;
        if (m >= M) continue;
#pragma unroll
        for (int j = 0; j < 4; j++) {
            int n = n0 + tx * 4 + j;
            if (n >= N) continue;
            float v = alpha * acc[i][j];
            if (bias) v += bias[n];
            if (kchunks == 1) C[(size_t)m * ldc + n] = v;
            else atomicAdd(&C[(size_t)m * ldc + n], v);
        }
    }
}

// ---------------- softmax over rows of g_scores (4096 rows x 1024) ---------
__global__ __launch_bounds__(256) void softmax_rows()
{
    int row = blockIdx.x;
    float* p = g_scores + (size_t)row * 1024;
    int tid = threadIdx.x;
    __shared__ float red[8];
    __shared__ float red2[8];

    float v[4];
    float mx = -1e30f;
#pragma unroll
    for (int i = 0; i < 4; i++) { v[i] = p[tid + i * 256]; mx = fmaxf(mx, v[i]); }
#pragma unroll
    for (int o = 16; o; o >>= 1) mx = fmaxf(mx, __shfl_xor_sync(0xffffffffu, mx, o));
    if ((tid & 31) == 0) red[tid >> 5] = mx;
    __syncthreads();
    float m2 = red[0];
#pragma unroll
    for (int w = 1; w < 8; w++) m2 = fmaxf(m2, red[w]);

    float s = 0.f;
#pragma unroll
    for (int i = 0; i < 4; i++) { v[i] = expf(v[i] - m2); s += v[i]; }
#pragma unroll
    for (int o = 16; o; o >>= 1) s += __shfl_xor_sync(0xffffffffu, s, o);
    if ((tid & 31) == 0) red2[tid >> 5] = s;
    __syncthreads();
    float tot = 0.f;
#pragma unroll
    for (int w = 0; w < 8; w++) tot += red2[w];
    float inv = 1.f / tot;
#pragma unroll
    for (int i = 0; i < 4; i++) p[tid + i * 256] = v[i] * inv;
}

// ---------------- attn_w mean over heads + zero ctx -------------------------
__global__ __launch_bounds__(256) void attn_mean(float* __restrict__ out)
{
    int idx = blockIdx.x * 256 + threadIdx.x;
    float s = g_scores[idx] + g_scores[idx + 1048576] +
              g_scores[idx + 2097152] + g_scores[idx + 3145728];
    out[idx] = 0.25f * s;
    if (blockIdx.x < 128)
        ((float4*)g_ctx)[idx] = make_float4(0.f, 0.f, 0.f, 0.f);
}

__global__ __launch_bounds__(256) void convert_bf(const float* __restrict__ W2)
{
    int idx = blockIdx.x * 256 + threadIdx.x;
    if (idx < NQ * CH) g_n1bf[idx] = __float2bfloat16(g_n1[idx]);
    if (idx < KO * CH) g_W2bf[idx] = __float2bfloat16(W2[idx]);
}

__global__ __launch_bounds__(256) void coord_kernel(
    const float* __restrict__ Wc1, const float* __restrict__ bc1,
    const float* __restrict__ Wc2, const float* __restrict__ bc2,
    float* __restrict__ out)
{
    __shared__ float ps[256];
    __shared__ float gs[128];
    __shared__ float h[256];
    int tid = threadIdx.x;
    int d = tid & 127, half = tid >> 7;
    float s = 0.f;
    for (int r = half * 512; r < half * 512 + 512; r++) s += g_att[r * 128 + d];
    ps[tid] = s;
    __syncthreads();
    if (tid < 128) gs[tid] = (ps[tid] + ps[tid + 128]) * (1.f / 1024.f);
    __syncthreads();
    float hv = bc1[tid];
    for (int c = 0; c < 128; c++) hv = fmaf(gs[c], Wc1[tid * 128 + c], hv);
    h[tid] = fmaxf(hv, 0.f);
    __syncthreads();
    if (tid < 32) {
        float z = bc2[tid];
        for (int c = 0; c < 256; c++) z = fmaf(h[c], Wc2[tid * 256 + c], z);
        out[tid] = z;
    }
}

// ============== persistent pairwise MLP (34.4 GMAC, bf16 mma.sync) ==========
// Grid = 152 persistent CTAs, ~54 tiles each. W2 staged to SMEM once per CTA.
// Per tile: A[128,256] bf16 = relu(t1+n1), HMMA M128 N128 K256, fused epilogue.
// k-loop software-pipelined (2-stage frags); next-tile t1/n1 prefetched via cp.async.

#define GRID_MATCH 152
#define NTILES 8192

#define SM_A 0
#define SM_B 67584
#define SM_T1_0 135168
#define SM_T1_1 143360
#define SM_N1_0 151552
#define SM_N1_1 159744
#define SM_W3 167936
#define SM_B2 168448
#define SM_ZP 168960
#define SMEM_TOTAL 169984
#define ROWSTRIDE_B 528  // 264 bf16/row; 132 words % 32 banks = 4 -> conflict-free ldmatrix

__device__ __forceinline__ void ldm_x4(uint32_t& r0, uint32_t& r1, uint32_t& r2, uint32_t& r3,
                                       uint32_t addr)
{
    asm volatile("ldmatrix.sync.aligned.m8n8.x4.shared.b16 {%0,%1,%2,%3}, [%4];"
                 : "=r"(r0), "=r"(r1), "=r"(r2), "=r"(r3)
                 : "r"(addr));
}

__device__ __forceinline__ void mma_bf16(float& c0, float& c1, float& c2, float& c3,
                                         uint32_t a0, uint32_t a1, uint32_t a2, uint32_t a3,
                                         uint32_t b0, uint32_t b1)
{
    asm volatile(
        "mma.sync.aligned.m16n8k16.row.col.f32.bf16.bf16.f32 "
        "{%0,%1,%2,%3}, {%4,%5,%6,%7}, {%8,%9}, {%0,%1,%2,%3};"
        : "+f"(c0), "+f"(c1), "+f"(c2), "+f"(c3)
        : "r"(a0), "r"(a1), "r"(a2), "r"(a3), "r"(b0), "r"(b1));
}

__device__ __forceinline__ uint32_t rp2(float a, float b, uint32_t nv)
{
    __nv_bfloat162 n = *reinterpret_cast<const __nv_bfloat162*>(&nv);
    float x0 = a + __bfloat162float(n.x);
    float x1 = b + __bfloat162float(n.y);
    __nv_bfloat162 o = __floats2bfloat162_rn(fmaxf(x0, 0.f), fmaxf(x1, 0.f));
    return *reinterpret_cast<uint32_t*>(&o);
}

__device__ __forceinline__ void cp16(uint32_t dst, const void* src)
{
    asm volatile("cp.async.cg.shared.global [%0], [%1], 16;" :: "r"(dst), "l"(src));
}
#define CP_COMMIT() asm volatile("cp.async.commit_group;" ::: "memory")
#define CP_WAIT0()  asm volatile("cp.async.wait_group 0;" ::: "memory")

__global__ __launch_bounds__(256, 1) void match_kernel(
    const float* __restrict__ W3, const float* __restrict__ b2v,
    const float* __restrict__ b3, float* __restrict__ out)
{
    extern __shared__ char sm[];
    float* sW3 = (float*)(sm + SM_W3);
    float* sb2 = (float*)(sm + SM_B2);
    float* zpart = (float*)(sm + SM_ZP);

    int tid = threadIdx.x;
    int lane = tid & 31, wid = tid >> 5;
    int wm = wid >> 1, wn = wid & 1;  // warp tile: M32 (wm), N64 (wn)

    const int t1Off[2] = {SM_T1_0, SM_T1_1};
    const int n1Off[2] = {SM_N1_0, SM_N1_1};
    uint32_t smuBase = (uint32_t)__cvta_generic_to_shared(sm);

    // ---- one-time staging: W2, W3, b2 ----
    {
        const uint4* bsrc = (const uint4*)g_W2bf;
#pragma unroll
        for (int j = 0; j < 16; j++) {
            int i = tid + j * 256;
            int r = i >> 5, q = i & 31;
            *(uint4*)(sm + SM_B + r * ROWSTRIDE_B + q * 16) = bsrc[i];
        }
        if (tid < 128) { sW3[tid] = W3[tid]; sb2[tid] = b2v[tid]; }
    }
    float b3v = b3[0];

    uint32_t aSm = (uint32_t)__cvta_generic_to_shared(sm + SM_A);
    uint32_t bSm = (uint32_t)__cvta_generic_to_shared(sm + SM_B);

    // ldmatrix base addresses (fixed for all tiles)
    uint32_t aBase[2];
#pragma unroll
    for (int mt = 0; mt < 2; mt++) {
        int row = wm * 32 + mt * 16 + (lane & 15);
        int colb = ((lane >> 4) << 3) * 2;
        aBase[mt] = aSm + row * ROWSTRIDE_B + colb;
    }
    uint32_t bBase[4];
#pragma unroll
    for (int nt2 = 0; nt2 < 4; nt2++) {
        int nrow = wn * 64 + nt2 * 16 + ((lane >> 4) << 3) + (lane & 7);
        int kb = (((lane >> 3) & 1) << 3) * 2;
        bBase[nt2] = bSm + nrow * ROWSTRIDE_B + kb;
    }
    __syncthreads();

    // ---- prologue: prefetch stage for first tile into buffer 0 ----
    int firstTile = blockIdx.x;
    if (firstTile < NTILES) {
        int t0 = (firstTile >> 6) * 8, n0 = (firstTile & 63) * 16;
        const float4* ts = (const float4*)(g_t1 + (size_t)t0 * 256);
        const uint4* ns = (const uint4*)(g_n1bf + (size_t)n0 * 256);
        cp16(smuBase + SM_T1_0 + tid * 16, ts + tid);
        cp16(smuBase + SM_T1_0 + (tid + 256) * 16, ts + tid + 256);
        cp16(smuBase + SM_N1_0 + tid * 16, ns + tid);
        cp16(smuBase + SM_N1_0 + (tid + 256) * 16, ns + tid + 256);
        CP_COMMIT();
    }

    int bi = 0;
    for (int tile = firstTile; tile < NTILES; tile += GRID_MATCH, bi ^= 1) {
        int n0 = (tile & 63) * 16, t0 = (tile >> 6) * 8;

        CP_WAIT0();
        __syncthreads();

        // ---- build A[r][c] = relu(t1[r/16][c] + n1[r%16][c]) bf16 ----
        {
            const float4* t1f4 = (const float4*)(sm + t1Off[bi]);
            const uint4* n1u4 = (const uint4*)(sm + n1Off[bi]);
#pragma unroll
            for (int j = 0; j < 16; j++) {
                int idx = tid + j * 256;
                int r = idx >> 5, q = idx & 31;
                int tl = r >> 4, nl = r & 15;
                float4 ta = t1f4[tl * 64 + q * 2];
                float4 tb = t1f4[tl * 64 + q * 2 + 1];
                uint4 nv = n1u4[nl * 32 + q];
                uint4 o;
                o.x = rp2(ta.x, ta.y, nv.x);
                o.y = rp2(ta.z, ta.w, nv.y);
                o.z = rp2(tb.x, tb.y, nv.z);
                o.w = rp2(tb.z, tb.w, nv.w);
                *(uint4*)(sm + SM_A + r * ROWSTRIDE_B + q * 16) = o;
            }
        }
        __syncthreads();

        // ---- prefetch next tile's t1/n1 into the other buffer ----
        int nextTile = tile + GRID_MATCH;
        if (nextTile < NTILES) {
            int nt0 = (nextTile >> 6) * 8, nn0 = (nextTile & 63) * 16;
            const float4* ts = (const float4*)(g_t1 + (size_t)nt0 * 256);
            const uint4* ns = (const uint4*)(g_n1bf + (size_t)nn0 * 256);
            int tb = t1Off[bi ^ 1], nb = n1Off[bi ^ 1];
            cp16(smuBase + tb + tid * 16, ts + tid);
            cp16(smuBase + tb + (tid + 256) * 16, ts + tid + 256);
            cp16(smuBase + nb + tid * 16, ns + tid);
            cp16(smuBase + nb + (tid + 256) * 16, ns + tid + 256);
        }
        CP_COMMIT();

        // ---- HMMA mainloop, 2-stage software pipeline ----
        float c[2][8][4];
#pragma unroll
        for (int mt = 0; mt < 2; mt++)
#pragma unroll
            for (int nt = 0; nt < 8; nt++)
#pragma unroll
                for (int j = 0; j < 4; j++) c[mt][nt][j] = 0.f;

        uint32_t a[2][2][4];
        uint32_t b[2][8][2];
        // load frags for kk = 0 into stage 0
#pragma unroll
        for (int mt = 0; mt < 2; mt++)
            ldm_x4(a[0][mt][0], a[0][mt][1], a[0][mt][2], a[0][mt][3], aBase[mt]);
#pragma unroll
        for (int nt2 = 0; nt2 < 4; nt2++) {
            uint32_t r0, r1, r2, r3;
            ldm_x4(r0, r1, r2, r3, bBase[nt2]);
            b[0][2 * nt2][0] = r0; b[0][2 * nt2][1] = r1;
            b[0][2 * nt2 + 1][0] = r2; b[0][2 * nt2 + 1][1] = r3;
        }

#pragma unroll
        for (int kk = 0; kk < 16; kk++) {
            int cur = kk & 1, nxt = cur ^ 1;
            if (kk < 15) {
                int ko = (kk + 1) * 32;
#pragma unroll
                for (int mt = 0; mt < 2; mt++)
                    ldm_x4(a[nxt][mt][0], a[nxt][mt][1], a[nxt][mt][2], a[nxt][mt][3],
                           aBase[mt] + ko);
#pragma unroll
                for (int nt2 = 0; nt2 < 4; nt2++) {
                    uint32_t r0, r1, r2, r3;
                    ldm_x4(r0, r1, r2, r3, bBase[nt2] + ko);
                    b[nxt][2 * nt2][0] = r0; b[nxt][2 * nt2][1] = r1;
                    b[nxt][2 * nt2 + 1][0] = r2; b[nxt][2 * nt2 + 1][1] = r3;
                }
            }
#pragma unroll
            for (int mt = 0; mt < 2; mt++)
#pragma unroll
                for (int nt = 0; nt < 8; nt++)
                    mma_bf16(c[mt][nt][0], c[mt][nt][1], c[mt][nt][2], c[mt][nt][3],
                             a[cur][mt][0], a[cur][mt][1], a[cur][mt][2], a[cur][mt][3],
                             b[cur][nt][0], b[cur][nt][1]);
        }

        // ---- epilogue: z[r] = sum_k relu(h2[r][k] + b2[k]) * W3[k] ----
        int g = lane >> 2, q = lane & 3;
#pragma unroll
        for (int mt = 0; mt < 2; mt++) {
            float p0 = 0.f, p1 = 0.f;
#pragma unroll
            for (int nt = 0; nt < 8; nt++) {
                int col = wn * 64 + nt * 8 + q * 2;
                float w0 = sW3[col], w1 = sW3[col + 1];
                float bb0 = sb2[col], bb1 = sb2[col + 1];
                p0 += fmaxf(c[mt][nt][0] + bb0, 0.f) * w0 + fmaxf(c[mt][nt][1] + bb1, 0.f) * w1;
                p1 += fmaxf(c[mt][nt][2] + bb0, 0.f) * w0 + fmaxf(c[mt][nt][3] + bb1, 0.f) * w1;
            }
            p0 += __shfl_xor_sync(0xffffffffu, p0, 1);
            p0 += __shfl_xor_sync(0xffffffffu, p0, 2);
            p1 += __shfl_xor_sync(0xffffffffu, p1, 1);
            p1 += __shfl_xor_sync(0xffffffffu, p1, 2);
            if (q == 0) {
                int rA = wm * 32 + mt * 16 + g;
                zpart[rA * 2 + wn] = p0;
                zpart[(rA + 8) * 2 + wn] = p1;
            }
        }
        __syncthreads();
        if (tid < 128) {
            float z = zpart[tid * 2] + zpart[tid * 2 + 1] + b3v;
            float s = 1.f / (1.f + expf(-z));
            int t = t0 + (tid >> 4), n = n0 + (tid & 15);
            out[(size_t)t * 1024 + n] = s;
        }
        __syncthreads();
    }
}

// ---------------- launch ---------------------------------------------------
extern "C" void kernel_launch(void* const* d_in, const int* in_sizes, int n_in,
                              void* d_out, int out_size)
{
    const float* node = (const float*)d_in[0];
    const float* task = (const float*)d_in[1];
    const float* ipw  = (const float*)d_in[2];
    const float* ipb  = (const float*)d_in[3];
    const float* outw = (const float*)d_in[4];
    const float* outb = (const float*)d_in[5];
    const float* W1   = (const float*)d_in[6];
    const float* b1   = (const float*)d_in[7];
    const float* W2   = (const float*)d_in[8];
    const float* b2   = (const float*)d_in[9];
    const float* W3   = (const float*)d_in[10];
    const float* b3   = (const float*)d_in[11];
    const float* Wc1  = (const float*)d_in[12];
    const float* bc1  = (const float*)d_in[13];
    const float* Wc2  = (const float*)d_in[14];
    const float* bc2  = (const float*)d_in[15];
    float* out = (float*)d_out;

    float *qkv, *t1, *scores, *ctx, *att, *n1;
    cudaGetSymbolAddress((void**)&qkv, g_qkv);
    cudaGetSymbolAddress((void**)&t1, g_t1);
    cudaGetSymbolAddress((void**)&scores, g_scores);
    cudaGetSymbolAddress((void**)&ctx, g_ctx);
    cudaGetSymbolAddress((void**)&att, g_att);
    cudaGetSymbolAddress((void**)&n1, g_n1);

    // QKV: node @ in_proj_w^T + b
    gemm_f32b<<<dim3(6, 16, 1), 256>>>(node, 128, 0, ipw, 128, 0, 1, ipb, 1.f,
                                       qkv, 384, 0, 1024, 384, 128, 1, 1);
    // t1 = task @ W1[:, :128]^T + b1
    gemm_f32b<<<dim3(4, 16, 1), 256>>>(task, 128, 0, W1, 256, 0, 1, b1, 1.f,
                                       t1, 256, 0, 1024, 256, 128, 1, 1);
    // scores: all 4 heads in one launch (z = head)
    gemm_f32b<<<dim3(16, 16, 4), 256>>>(qkv, 384, 32, qkv + 128, 384, 32, 1,
                                        nullptr, 0.17677669529663687f,
                                        scores, 1024, 1048576, 1024, 1024, 32, 4, 1);
    softmax_rows<<<4096, 256>>>();
    attn_mean<<<4096, 256>>>(out + 1048608);   // also zeroes g_ctx
    // ctx: 4 heads x split-K(4) with atomic accumulation
    gemm_f32b<<<dim3(1, 16, 16), 256>>>(scores, 1024, 1048576, qkv + 256, 384, 32, 0,
                                        nullptr, 1.f, ctx, 128, 32,
                                        1024, 32, 1024, 4, 4);
    // attended = ctx @ out_w^T + out_b
    gemm_f32b<<<dim3(2, 16, 1), 256>>>(ctx, 128, 0, outw, 128, 0, 1, outb, 1.f,
                                       att, 128, 0, 1024, 128, 128, 1, 1);
    // n1 = attended @ W1[:, 128:]^T
    gemm_f32b<<<dim3(4, 16, 1), 256>>>(att, 128, 0, W1 + 128, 256, 0, 1, nullptr, 1.f,
                                       n1, 256, 0, 1024, 256, 128, 1, 1);
    convert_bf<<<1024, 256>>>(W2);
    // persistent bf16 HMMA pairwise MLP
    cudaFuncSetAttribute(match_kernel, cudaFuncAttributeMaxDynamicSharedMemorySize, SMEM_TOTAL);
    match_kernel<<<GRID_MATCH, 256, SMEM_TOTAL>>>(W3, b2, b3, out);
    // coordination head
    coord_kernel<<<1, 256>>>(Wc1, bc1, Wc2, bc2, out + 1048576);
}

// round 11
// speedup vs baseline: 2.7025x; 1.0747x over previous
#include <cuda_runtime.h>
#include <cuda_bf16.h>
#include <math.h>
#include <stdint.h>

#define NQ 1024
#define TT 1024
#define DM 128
#define CH 256
#define KO 128

// ---------------- scratch (static device memory; no allocs) ----------------
__device__ float g_qkv[NQ * 384];
__device__ float g_t1[TT * CH];
__device__ float g_scores[4 * NQ * NQ];
__device__ float g_ctx[NQ * DM];
__device__ float g_att[NQ * DM];
__device__ __nv_bfloat16 g_n1bf[NQ * CH];
__device__ __nv_bfloat16 g_W2bf[KO * CH];

// ---------------- fused QKV + t1 projections (z selects problem) -----------
__global__ __launch_bounds__(256) void qkv_t1_kernel(
    const float* __restrict__ node, const float* __restrict__ ipw, const float* __restrict__ ipb,
    const float* __restrict__ task, const float* __restrict__ W1, const float* __restrict__ b1)
{
    __shared__ float As[16][68];
    __shared__ float Bs[16][68];
    const float *A, *B, *bias;
    float* C;
    int ldb, ldc;
    if (blockIdx.z == 0) { A = node; B = ipw; bias = ipb; C = g_qkv; ldb = 128; ldc = 384; }
    else { if (blockIdx.x >= 4) return;
           A = task; B = W1; bias = b1; C = g_t1; ldb = 256; ldc = 256; }
    int tid = threadIdx.x, tx = tid & 15, ty = tid >> 4;
    int m0 = blockIdx.y * 64, n0 = blockIdx.x * 64;

    float acc[4][4];
#pragma unroll
    for (int i = 0; i < 4; i++)
#pragma unroll
        for (int j = 0; j < 4; j++) acc[i][j] = 0.f;

    for (int k0 = 0; k0 < 128; k0 += 16) {
#pragma unroll
        for (int it = 0; it < 4; it++) {
            int idx = tid + it * 256;
            As[idx & 15][idx >> 4] = A[(size_t)(m0 + (idx >> 4)) * 128 + k0 + (idx & 15)];
        }
#pragma unroll
        for (int it = 0; it < 4; it++) {
            int idx = tid + it * 256;
            Bs[idx & 15][idx >> 4] = B[(size_t)(n0 + (idx >> 4)) * ldb + k0 + (idx & 15)];
        }
        __syncthreads();
#pragma unroll
        for (int k = 0; k < 16; k++) {
            float4 a = *(const float4*)&As[k][ty * 4];
            float4 b = *(const float4*)&Bs[k][tx * 4];
            float av[4] = {a.x, a.y, a.z, a.w};
            float bv[4] = {b.x, b.y, b.z, b.w};
#pragma unroll
            for (int i = 0; i < 4; i++)
#pragma unroll
                for (int j = 0; j < 4; j++) acc[i][j] = fmaf(av[i], bv[j], acc[i][j]);
        }
        __syncthreads();
    }
#pragma unroll
    for (int i = 0; i < 4; i++)
#pragma unroll
        for (int j = 0; j < 4; j++) {
            int n = n0 + tx * 4 + j;
            C[(size_t)(m0 + ty * 4 + i) * ldc + n] = acc[i][j] + bias[n];
        }
}

// ---------------- batched fp32 GEMM with optional split-K (scores, ctx) -----
__global__ __launch_bounds__(256) void gemm_f32b(
    const float* __restrict__ A, int lda, int sAz,
    const float* __restrict__ B, int ldb, int sBz, int transB,
    const float* __restrict__ bias, float alpha,
    float* __restrict__ C, int ldc, int sCz,
    int M, int N, int K, int nz, int kchunks)
{
    __shared__ float As[16][68];
    __shared__ float Bs[16][68];
    int tid = threadIdx.x;
    int tx = tid & 15, ty = tid >> 4;
    int m0 = blockIdx.y * 64, n0 = blockIdx.x * 64;
    int h = blockIdx.z % nz, kc = blockIdx.z / nz;
    A += (size_t)h * sAz; B += (size_t)h * sBz; C += (size_t)h * sCz;
    int KC = K / kchunks;
    int kLo = kc * KC, kHi = kLo + KC;

    float acc[4][4];
#pragma unroll
    for (int i = 0; i < 4; i++)
#pragma unroll
        for (int j = 0; j < 4; j++) acc[i][j] = 0.f;

    for (int k0 = kLo; k0 < kHi; k0 += 16) {
#pragma unroll
        for (int it = 0; it < 4; it++) {
            int idx = tid + it * 256;
            int k = idx & 15, m = idx >> 4;
            float v = 0.f;
            if (m0 + m < M && k0 + k < K) v = A[(size_t)(m0 + m) * lda + k0 + k];
            As[k][m] = v;
        }
        if (transB) {
#pragma unroll
            for (int it = 0; it < 4; it++) {
                int idx = tid + it * 256;
                int k = idx & 15, n = idx >> 4;
                float v = 0.f;
                if (n0 + n < N && k0 + k < K) v = B[(size_t)(n0 + n) * ldb + k0 + k];
                Bs[k][n] = v;
            }
        } else {
#pragma unroll
            for (int it = 0; it < 4; it++) {
                int idx = tid + it * 256;
                int n = idx & 63, k = idx >> 6;
                float v = 0.f;
                if (k0 + k < K && n0 + n < N) v = B[(size_t)(k0 + k) * ldb + n0 + n];
                Bs[k][n] = v;
            }
        }
        __syncthreads();
#pragma unroll
        for (int k = 0; k < 16; k++) {
            float4 a = *(const float4*)&As[k][ty * 4];
            float4 b = *(const float4*)&Bs[k][tx * 4];
            float av[4] = {a.x, a.y, a.z, a.w};
            float bv[4] = {b.x, b.y, b.z, b.w};
#pragma unroll
            for (int i = 0; i < 4; i++)
#pragma unroll
                for (int j = 0; j < 4; j++) acc[i][j] = fmaf(av[i], bv[j], acc[i][j]);
        }
        __syncthreads();
    }

#pragma unroll
    for (int i = 0; i < 4; i++) {
        int m = m0 + ty * 4 + i;
        if (m >= M) continue;
#pragma unroll
        for (int j = 0; j < 4; j++) {
            int n = n0 + tx * 4 + j;
            if (n >= N) continue;
            float v = alpha * acc[i][j];
            if (bias) v += bias[n];
            if (kchunks == 1) C[(size_t)m * ldc + n] = v;
            else atomicAdd(&C[(size_t)m * ldc + n], v);
        }
    }
}

// ------- fused softmax (4 heads per row) + head-mean + ctx zero + W2->bf16 --
__global__ __launch_bounds__(256) void softmax_fused(
    const float* __restrict__ W2, float* __restrict__ out)
{
    int row = blockIdx.x, tid = threadIdx.x;
    __shared__ float red[8];
    __shared__ float red2[8];
    float acc[4] = {0.f, 0.f, 0.f, 0.f};

#pragma unroll
    for (int h = 0; h < 4; h++) {
        float* p = g_scores + (size_t)h * 1048576 + (size_t)row * 1024;
        float v[4];
        float mx = -1e30f;
#pragma unroll
        for (int i = 0; i < 4; i++) { v[i] = p[tid + i * 256]; mx = fmaxf(mx, v[i]); }
#pragma unroll
        for (int o = 16; o; o >>= 1) mx = fmaxf(mx, __shfl_xor_sync(0xffffffffu, mx, o));
        __syncthreads();   // protect red reuse across h
        if ((tid & 31) == 0) red[tid >> 5] = mx;
        __syncthreads();
        float m2 = red[0];
#pragma unroll
        for (int w = 1; w < 8; w++) m2 = fmaxf(m2, red[w]);

        float s = 0.f;
#pragma unroll
        for (int i = 0; i < 4; i++) { v[i] = expf(v[i] - m2); s += v[i]; }
#pragma unroll
        for (int o = 16; o; o >>= 1) s += __shfl_xor_sync(0xffffffffu, s, o);
        if ((tid & 31) == 0) red2[tid >> 5] = s;
        __syncthreads();
        float tot = 0.f;
#pragma unroll
        for (int w = 0; w < 8; w++) tot += red2[w];
        float inv = 1.f / tot;
#pragma unroll
        for (int i = 0; i < 4; i++) {
            float pv = v[i] * inv;
            p[tid + i * 256] = pv;
            acc[i] += pv;
        }
    }
#pragma unroll
    for (int i = 0; i < 4; i++)
        out[(size_t)row * 1024 + tid + i * 256] = 0.25f * acc[i];
    if (tid < 128) g_ctx[row * 128 + tid] = 0.f;
    if (row < 128) g_W2bf[row * 256 + tid] = __float2bfloat16(W2[row * 256 + tid]);
}

// ------- fused attended-projection + n1 + bf16 convert ----------------------
// grid (4,16): each CTA computes att rows [by*64, +64) x all 128 cols (x-redundant),
// bx==0 writes g_att; every CTA then computes n1bf chunk [by*64,+64) x [bx*64,+64).
__global__ __launch_bounds__(256) void att_n1(
    const float* __restrict__ outw, const float* __restrict__ outb,
    const float* __restrict__ W1)
{
    __shared__ float As[16][68];
    __shared__ float Bs[16][132];
    __shared__ float att_s[64][133];
    int tid = threadIdx.x, tx = tid & 15, ty = tid >> 4;
    int m0 = blockIdx.y * 64, n0 = blockIdx.x * 64;

    // ---- phase 1: att = ctx @ outw^T + outb, 64 x 128 ----
    float a8[4][8];
#pragma unroll
    for (int i = 0; i < 4; i++)
#pragma unroll
        for (int j = 0; j < 8; j++) a8[i][j] = 0.f;

    for (int k0 = 0; k0 < 128; k0 += 16) {
#pragma unroll
        for (int it = 0; it < 4; it++) {
            int idx = tid + it * 256;
            As[idx & 15][idx >> 4] = g_ctx[(size_t)(m0 + (idx >> 4)) * 128 + k0 + (idx & 15)];
        }
#pragma unroll
        for (int it = 0; it < 8; it++) {
            int idx = tid + it * 256;
            int n = idx & 127, k = idx >> 7;
            Bs[k][n] = outw[(size_t)n * 128 + k0 + k];
        }
        __syncthreads();
#pragma unroll
        for (int k = 0; k < 16; k++) {
            float4 a = *(const float4*)&As[k][ty * 4];
            float4 b0 = *(const float4*)&Bs[k][tx * 8];
            float4 b1 = *(const float4*)&Bs[k][tx * 8 + 4];
            float av[4] = {a.x, a.y, a.z, a.w};
            float bv[8] = {b0.x, b0.y, b0.z, b0.w, b1.x, b1.y, b1.z, b1.w};
#pragma unroll
            for (int i = 0; i < 4; i++)
#pragma unroll
                for (int j = 0; j < 8; j++) a8[i][j] = fmaf(av[i], bv[j], a8[i][j]);
        }
        __syncthreads();
    }
#pragma unroll
    for (int i = 0; i < 4; i++) {
        int m = ty * 4 + i;
#pragma unroll
        for (int j = 0; j < 8; j++) {
            int col = tx * 8 + j;
            float v = a8[i][j] + outb[col];
            att_s[m][col] = v;
            if (blockIdx.x == 0) g_att[(size_t)(m0 + m) * 128 + col] = v;
        }
    }
    __syncthreads();

    // ---- phase 2: n1 = att @ W1[:,128:]^T (no bias), 64 x 64 chunk -> bf16 ----
    float c2[4][4];
#pragma unroll
    for (int i = 0; i < 4; i++)
#pragma unroll
        for (int j = 0; j < 4; j++) c2[i][j] = 0.f;

    for (int k0 = 0; k0 < 128; k0 += 16) {
#pragma unroll
        for (int it = 0; it < 4; it++) {
            int idx = tid + it * 256;
            As[idx & 15][idx >> 4] = W1[(size_t)(n0 + (idx >> 4)) * 256 + 128 + k0 + (idx & 15)];
        }
        __syncthreads();
#pragma unroll
        for (int k = 0; k < 16; k++) {
            float4 b = *(const float4*)&As[k][tx * 4];
            float bv[4] = {b.x, b.y, b.z, b.w};
#pragma unroll
            for (int i = 0; i < 4; i++) {
                float av = att_s[ty * 4 + i][k0 + k];
#pragma unroll
                for (int j = 0; j < 4; j++) c2[i][j] = fmaf(av, bv[j], c2[i][j]);
            }
        }
        __syncthreads();
    }
#pragma unroll
    for (int i = 0; i < 4; i++) {
        int m = m0 + ty * 4 + i;
        __nv_bfloat162 lo = __floats2bfloat162_rn(c2[i][0], c2[i][1]);
        __nv_bfloat162 hi = __floats2bfloat162_rn(c2[i][2], c2[i][3]);
        *(uint32_t*)&g_n1bf[(size_t)m * 256 + n0 + tx * 4] = *(uint32_t*)&lo;
        *(uint32_t*)&g_n1bf[(size_t)m * 256 + n0 + tx * 4 + 2] = *(uint32_t*)&hi;
    }
}

// ---------------- coordination head ----------------------------------------
__global__ __launch_bounds__(256) void coord_kernel(
    const float* __restrict__ Wc1, const float* __restrict__ bc1,
    const float* __restrict__ Wc2, const float* __restrict__ bc2,
    float* __restrict__ out)
{
    __shared__ float ps[256];
    __shared__ float gs[128];
    __shared__ float h[256];
    int tid = threadIdx.x;
    int d = tid & 127, half = tid >> 7;
    float s = 0.f;
    for (int r = half * 512; r < half * 512 + 512; r++) s += g_att[r * 128 + d];
    ps[tid] = s;
    __syncthreads();
    if (tid < 128) gs[tid] = (ps[tid] + ps[tid + 128]) * (1.f / 1024.f);
    __syncthreads();
    float hv = bc1[tid];
    for (int c = 0; c < 128; c++) hv = fmaf(gs[c], Wc1[tid * 128 + c], hv);
    h[tid] = fmaxf(hv, 0.f);
    __syncthreads();
    if (tid < 32) {
        float z = bc2[tid];
        for (int c = 0; c < 256; c++) z = fmaf(h[c], Wc2[tid * 256 + c], z);
        out[tid] = z;
    }
}

// ============== persistent pairwise MLP (34.4 GMAC, bf16 mma.sync) ==========
#define GRID_MATCH 152
#define NTILES 8192

#define SM_A 0
#define SM_B 67584
#define SM_T1_0 135168
#define SM_T1_1 143360
#define SM_N1_0 151552
#define SM_N1_1 160256
#define SM_W3 168960
#define SM_B2 169472
#define SM_ZP 169984
#define SMEM_TOTAL 171008
#define ROWSTRIDE_B 528  // 264 bf16/row; conflict-free ldmatrix/LDS/STS
#define N1STRIDE 528     // n1 staged rows padded to 528B for conflict-free build reads

__device__ __forceinline__ void ldm_x4(uint32_t& r0, uint32_t& r1, uint32_t& r2, uint32_t& r3,
                                       uint32_t addr)
{
    asm volatile("ldmatrix.sync.aligned.m8n8.x4.shared.b16 {%0,%1,%2,%3}, [%4];"
                 : "=r"(r0), "=r"(r1), "=r"(r2), "=r"(r3)
                 : "r"(addr));
}

__device__ __forceinline__ void mma_bf16(float& c0, float& c1, float& c2, float& c3,
                                         uint32_t a0, uint32_t a1, uint32_t a2, uint32_t a3,
                                         uint32_t b0, uint32_t b1)
{
    asm volatile(
        "mma.sync.aligned.m16n8k16.row.col.f32.bf16.bf16.f32 "
        "{%0,%1,%2,%3}, {%4,%5,%6,%7}, {%8,%9}, {%0,%1,%2,%3};"
        : "+f"(c0), "+f"(c1), "+f"(c2), "+f"(c3)
        : "r"(a0), "r"(a1), "r"(a2), "r"(a3), "r"(b0), "r"(b1));
}

__device__ __forceinline__ uint32_t rp2(float a, float b, uint32_t nv)
{
    __nv_bfloat162 n = *reinterpret_cast<const __nv_bfloat162*>(&nv);
    float x0 = a + __bfloat162float(n.x);
    float x1 = b + __bfloat162float(n.y);
    __nv_bfloat162 o = __floats2bfloat162_rn(fmaxf(x0, 0.f), fmaxf(x1, 0.f));
    return *reinterpret_cast<uint32_t*>(&o);
}

__device__ __forceinline__ void cp16(uint32_t dst, const void* src)
{
    asm volatile("cp.async.cg.shared.global [%0], [%1], 16;" :: "r"(dst), "l"(src));
}
#define CP_COMMIT() asm volatile("cp.async.commit_group;" ::: "memory")
#define CP_WAIT0()  asm volatile("cp.async.wait_group 0;" ::: "memory")

__global__ __launch_bounds__(256, 1) void match_kernel(
    const float* __restrict__ W3, const float* __restrict__ b2v,
    const float* __restrict__ b3, float* __restrict__ out)
{
    extern __shared__ char sm[];
    float* sW3 = (float*)(sm + SM_W3);
    float* sb2 = (float*)(sm + SM_B2);
    float* zpart = (float*)(sm + SM_ZP);

    int tid = threadIdx.x;
    int lane = tid & 31, wid = tid >> 5;
    int wm = wid >> 1, wn = wid & 1;  // warp tile: M32 (wm), N64 (wn)

    const int t1Off[2] = {SM_T1_0, SM_T1_1};
    const int n1Off[2] = {SM_N1_0, SM_N1_1};
    uint32_t smuBase = (uint32_t)__cvta_generic_to_shared(sm);

    // ---- one-time staging: W2, W3, b2 ----
    {
        const uint4* bsrc = (const uint4*)g_W2bf;
#pragma unroll
        for (int j = 0; j < 16; j++) {
            int i = tid + j * 256;
            int r = i >> 5, q = i & 31;
            *(uint4*)(sm + SM_B + r * ROWSTRIDE_B + q * 16) = bsrc[i];
        }
        if (tid < 128) { sW3[tid] = W3[tid]; sb2[tid] = b2v[tid]; }
    }
    float b3v = b3[0];

    uint32_t aSm = (uint32_t)__cvta_generic_to_shared(sm + SM_A);
    uint32_t bSm = (uint32_t)__cvta_generic_to_shared(sm + SM_B);

    uint32_t aBase[2];
#pragma unroll
    for (int mt = 0; mt < 2; mt++) {
        int row = wm * 32 + mt * 16 + (lane & 15);
        int colb = ((lane >> 4) << 3) * 2;
        aBase[mt] = aSm + row * ROWSTRIDE_B + colb;
    }
    uint32_t bBase[4];
#pragma unroll
    for (int nt2 = 0; nt2 < 4; nt2++) {
        int nrow = wn * 64 + nt2 * 16 + ((lane >> 4) << 3) + (lane & 7);
        int kb = (((lane >> 3) & 1) << 3) * 2;
        bBase[nt2] = bSm + nrow * ROWSTRIDE_B + kb;
    }
    __syncthreads();

    // ---- prologue: prefetch first tile's t1/n1 into buffer 0 ----
    int firstTile = blockIdx.x;
    if (firstTile < NTILES) {
        int t0 = (firstTile >> 6) * 8, n0 = (firstTile & 63) * 16;
        const float4* ts = (const float4*)(g_t1 + (size_t)t0 * 256);
        const uint4* ns = (const uint4*)(g_n1bf + (size_t)n0 * 256);
        cp16(smuBase + SM_T1_0 + tid * 16, ts + tid);
        cp16(smuBase + SM_T1_0 + (tid + 256) * 16, ts + tid + 256);
        {
            int i0 = tid, i1 = tid + 256;
            cp16(smuBase + SM_N1_0 + (i0 >> 5) * N1STRIDE + (i0 & 31) * 16, ns + i0);
            cp16(smuBase + SM_N1_0 + (i1 >> 5) * N1STRIDE + (i1 & 31) * 16, ns + i1);
        }
        CP_COMMIT();
    }

    int bi = 0;
    for (int tile = firstTile; tile < NTILES; tile += GRID_MATCH, bi ^= 1) {
        int n0 = (tile & 63) * 16, t0 = (tile >> 6) * 8;

        CP_WAIT0();
        __syncthreads();

        // ---- build A[r][c] = relu(t1[r/16][c] + n1[r%16][c]) bf16 ----
        // r = tid&127 (warp-contiguous), q parity = tid>>7: conflict-free LDS/STS.
        {
            const float4* t1f4 = (const float4*)(sm + t1Off[bi]);
            const char* n1b = sm + n1Off[bi];
            int r = tid & 127, qp = tid >> 7;
            int tl = r >> 4, nl = r & 15;
            const char* n1row = n1b + nl * N1STRIDE;
            char* aRow = sm + SM_A + r * ROWSTRIDE_B;
            const float4* t1row = t1f4 + tl * 64;
#pragma unroll
            for (int j = 0; j < 16; j++) {
                int q = qp + 2 * j;
                float4 ta = t1row[q * 2];
                float4 tb = t1row[q * 2 + 1];
                uint4 nv = *(const uint4*)(n1row + q * 16);
                uint4 o;
                o.x = rp2(ta.x, ta.y, nv.x);
                o.y = rp2(ta.z, ta.w, nv.y);
                o.z = rp2(tb.x, tb.y, nv.z);
                o.w = rp2(tb.z, tb.w, nv.w);
                *(uint4*)(aRow + q * 16) = o;
            }
        }
        __syncthreads();

        // ---- prefetch next tile's t1/n1 into the other buffer ----
        int nextTile = tile + GRID_MATCH;
        if (nextTile < NTILES) {
            int nt0 = (nextTile >> 6) * 8, nn0 = (nextTile & 63) * 16;
            const float4* ts = (const float4*)(g_t1 + (size_t)nt0 * 256);
            const uint4* ns = (const uint4*)(g_n1bf + (size_t)nn0 * 256);
            int tb = t1Off[bi ^ 1], nb = n1Off[bi ^ 1];
            cp16(smuBase + tb + tid * 16, ts + tid);
            cp16(smuBase + tb + (tid + 256) * 16, ts + tid + 256);
            int i0 = tid, i1 = tid + 256;
            cp16(smuBase + nb + (i0 >> 5) * N1STRIDE + (i0 & 31) * 16, ns + i0);
            cp16(smuBase + nb + (i1 >> 5) * N1STRIDE + (i1 & 31) * 16, ns + i1);
        }
        CP_COMMIT();

        // ---- HMMA mainloop, 2-stage software pipeline ----
        float c[2][8][4];
#pragma unroll
        for (int mt = 0; mt < 2; mt++)
#pragma unroll
            for (int nt = 0; nt < 8; nt++)
#pragma unroll
                for (int j = 0; j < 4; j++) c[mt][nt][j] = 0.f;

        uint32_t a[2][2][4];
        uint32_t b[2][8][2];
#pragma unroll
        for (int mt = 0; mt < 2; mt++)
            ldm_x4(a[0][mt][0], a[0][mt][1], a[0][mt][2], a[0][mt][3], aBase[mt]);
#pragma unroll
        for (int nt2 = 0; nt2 < 4; nt2++) {
            uint32_t r0, r1, r2, r3;
            ldm_x4(r0, r1, r2, r3, bBase[nt2]);
            b[0][2 * nt2][0] = r0; b[0][2 * nt2][1] = r1;
            b[0][2 * nt2 + 1][0] = r2; b[0][2 * nt2 + 1][1] = r3;
        }

#pragma unroll
        for (int kk = 0; kk < 16; kk++) {
            int cur = kk & 1, nxt = cur ^ 1;
            if (kk < 15) {
                int ko = (kk + 1) * 32;
#pragma unroll
                for (int mt = 0; mt < 2; mt++)
                    ldm_x4(a[nxt][mt][0], a[nxt][mt][1], a[nxt][mt][2], a[nxt][mt][3],
                           aBase[mt] + ko);
#pragma unroll
                for (int nt2 = 0; nt2 < 4; nt2++) {
                    uint32_t r0, r1, r2, r3;
                    ldm_x4(r0, r1, r2, r3, bBase[nt2] + ko);
                    b[nxt][2 * nt2][0] = r0; b[nxt][2 * nt2][1] = r1;
                    b[nxt][2 * nt2 + 1][0] = r2; b[nxt][2 * nt2 + 1][1] = r3;
                }
            }
#pragma unroll
            for (int mt = 0; mt < 2; mt++)
#pragma unroll
                for (int nt = 0; nt < 8; nt++)
                    mma_bf16(c[mt][nt][0], c[mt][nt][1], c[mt][nt][2], c[mt][nt][3],
                             a[cur][mt][0], a[cur][mt][1], a[cur][mt][2], a[cur][mt][3],
                             b[cur][nt][0], b[cur][nt][1]);
        }

        // ---- epilogue: z[r] = sum_k relu(h2[r][k] + b2[k]) * W3[k] ----
        int g = lane >> 2, q = lane & 3;
#pragma unroll
        for (int mt = 0; mt < 2; mt++) {
            float p0 = 0.f, p1 = 0.f;
#pragma unroll
            for (int nt = 0; nt < 8; nt++) {
                int col = wn * 64 + nt * 8 + q * 2;
                float w0 = sW3[col], w1 = sW3[col + 1];
                float bb0 = sb2[col], bb1 = sb2[col + 1];
                p0 += fmaxf(c[mt][nt][0] + bb0, 0.f) * w0 + fmaxf(c[mt][nt][1] + bb1, 0.f) * w1;
                p1 += fmaxf(c[mt][nt][2] + bb0, 0.f) * w0 + fmaxf(c[mt][nt][3] + bb1, 0.f) * w1;
            }
            p0 += __shfl_xor_sync(0xffffffffu, p0, 1);
            p0 += __shfl_xor_sync(0xffffffffu, p0, 2);
            p1 += __shfl_xor_sync(0xffffffffu, p1, 1);
            p1 += __shfl_xor_sync(0xffffffffu, p1, 2);
            if (q == 0) {
                int rA = wm * 32 + mt * 16 + g;
                zpart[rA * 2 + wn] = p0;
                zpart[(rA + 8) * 2 + wn] = p1;
            }
        }
        __syncthreads();
        if (tid < 128) {
            float z = zpart[tid * 2] + zpart[tid * 2 + 1] + b3v;
            float s = 1.f / (1.f + expf(-z));
            int t = t0 + (tid >> 4), n = n0 + (tid & 15);
            out[(size_t)t * 1024 + n] = s;
        }
        __syncthreads();
    }
}

// ---------------- launch ---------------------------------------------------
extern "C" void kernel_launch(void* const* d_in, const int* in_sizes, int n_in,
                              void* d_out, int out_size)
{
    const float* node = (const float*)d_in[0];
    const float* task = (const float*)d_in[1];
    const float* ipw  = (const float*)d_in[2];
    const float* ipb  = (const float*)d_in[3];
    const float* outw = (const float*)d_in[4];
    const float* outb = (const float*)d_in[5];
    const float* W1   = (const float*)d_in[6];
    const float* b1   = (const float*)d_in[7];
    const float* W2   = (const float*)d_in[8];
    const float* b2   = (const float*)d_in[9];
    const float* W3   = (const float*)d_in[10];
    const float* b3   = (const float*)d_in[11];
    const float* Wc1  = (const float*)d_in[12];
    const float* bc1  = (const float*)d_in[13];
    const float* Wc2  = (const float*)d_in[14];
    const float* bc2  = (const float*)d_in[15];
    float* out = (float*)d_out;

    float *qkv, *scores, *ctx;
    cudaGetSymbolAddress((void**)&qkv, g_qkv);
    cudaGetSymbolAddress((void**)&scores, g_scores);
    cudaGetSymbolAddress((void**)&ctx, g_ctx);

    // 0: QKV + t1 fused
    qkv_t1_kernel<<<dim3(6, 16, 2), 256>>>(node, ipw, ipb, task, W1, b1);
    // 1: scores (all 4 heads)
    gemm_f32b<<<dim3(16, 16, 4), 256>>>(qkv, 384, 32, qkv + 128, 384, 32, 1,
                                        nullptr, 0.17677669529663687f,
                                        scores, 1024, 1048576, 1024, 1024, 32, 4, 1);
    // 2: softmax + head-mean + ctx zero + W2->bf16
    softmax_fused<<<1024, 256>>>(W2, out + 1048608);
    // 3: ctx (4 heads x split-K 4, atomic)
    gemm_f32b<<<dim3(1, 16, 16), 256>>>(scores, 1024, 1048576, qkv + 256, 384, 32, 0,
                                        nullptr, 1.f, ctx, 128, 32,
                                        1024, 32, 1024, 4, 4);
    // 4: attended projection + n1 (bf16) fused
    att_n1<<<dim3(4, 16), 256>>>(outw, outb, W1);
    // 5: persistent bf16 HMMA pairwise MLP
    cudaFuncSetAttribute(match_kernel, cudaFuncAttributeMaxDynamicSharedMemorySize, SMEM_TOTAL);
    match_kernel<<<GRID_MATCH, 256, SMEM_TOTAL>>>(W3, b2, b3, out);
    // 6: coordination head
    coord_kernel<<<1, 256>>>(Wc1, bc1, Wc2, bc2, out + 1048576);
}

// round 13
// speedup vs baseline: 2.8276x; 1.0463x over previous
#include <cuda_runtime.h>
#include <cuda_bf16.h>
#include <math.h>
#include <stdint.h>

#define NQ 1024
#define TT 1024
#define DM 128
#define CH 256
#define KO 128

// ---------------- scratch (static device memory; no allocs) ----------------
__device__ float g_qkv[NQ * 384];
__device__ float g_t1[TT * CH];
__device__ float g_scores[4 * NQ * NQ];
__device__ float g_ctxp[4][NQ * DM];   // split-K partials (deterministic)
__device__ float g_att[NQ * DM];
__device__ __nv_bfloat16 g_n1bf[NQ * CH];
__device__ __nv_bfloat16 g_W2bf[KO * CH];

// ---------------- fused QKV + t1 projections (z selects problem) -----------
__global__ __launch_bounds__(256) void qkv_t1_kernel(
    const float* __restrict__ node, const float* __restrict__ ipw, const float* __restrict__ ipb,
    const float* __restrict__ task, const float* __restrict__ W1, const float* __restrict__ b1)
{
    __shared__ float As[16][68];
    __shared__ float Bs[16][68];
    const float *A, *B, *bias;
    float* C;
    int ldb, ldc;
    if (blockIdx.z == 0) { A = node; B = ipw; bias = ipb; C = g_qkv; ldb = 128; ldc = 384; }
    else { if (blockIdx.x >= 4) return;
           A = task; B = W1; bias = b1; C = g_t1; ldb = 256; ldc = 256; }
    int tid = threadIdx.x, tx = tid & 15, ty = tid >> 4;
    int m0 = blockIdx.y * 64, n0 = blockIdx.x * 64;

    float acc[4][4];
#pragma unroll
    for (int i = 0; i < 4; i++)
#pragma unroll
        for (int j = 0; j < 4; j++) acc[i][j] = 0.f;

    for (int k0 = 0; k0 < 128; k0 += 16) {
#pragma unroll
        for (int it = 0; it < 4; it++) {
            int idx = tid + it * 256;
            As[idx & 15][idx >> 4] = A[(size_t)(m0 + (idx >> 4)) * 128 + k0 + (idx & 15)];
        }
#pragma unroll
        for (int it = 0; it < 4; it++) {
            int idx = tid + it * 256;
            Bs[idx & 15][idx >> 4] = B[(size_t)(n0 + (idx >> 4)) * ldb + k0 + (idx & 15)];
        }
        __syncthreads();
#pragma unroll
        for (int k = 0; k < 16; k++) {
            float4 a = *(const float4*)&As[k][ty * 4];
            float4 b = *(const float4*)&Bs[k][tx * 4];
            float av[4] = {a.x, a.y, a.z, a.w};
            float bv[4] = {b.x, b.y, b.z, b.w};
#pragma unroll
            for (int i = 0; i < 4; i++)
#pragma unroll
                for (int j = 0; j < 4; j++) acc[i][j] = fmaf(av[i], bv[j], acc[i][j]);
        }
        __syncthreads();
    }
#pragma unroll
    for (int i = 0; i < 4; i++)
#pragma unroll
        for (int j = 0; j < 4; j++) {
            int n = n0 + tx * 4 + j;
            C[(size_t)(m0 + ty * 4 + i) * ldc + n] = acc[i][j] + bias[n];
        }
}

// ---------------- scores GEMM (batched over heads) --------------------------
__global__ __launch_bounds__(256) void gemm_f32b(
    const float* __restrict__ A, int lda, int sAz,
    const float* __restrict__ B, int ldb, int sBz,
    float alpha, float* __restrict__ C, int ldc, int sCz, int K)
{
    __shared__ float As[16][68];
    __shared__ float Bs[16][68];
    int tid = threadIdx.x;
    int tx = tid & 15, ty = tid >> 4;
    int m0 = blockIdx.y * 64, n0 = blockIdx.x * 64;
    int h = blockIdx.z;
    A += (size_t)h * sAz; B += (size_t)h * sBz; C += (size_t)h * sCz;

    float acc[4][4];
#pragma unroll
    for (int i = 0; i < 4; i++)
#pragma unroll
        for (int j = 0; j < 4; j++) acc[i][j] = 0.f;

    for (int k0 = 0; k0 < K; k0 += 16) {
#pragma unroll
        for (int it = 0; it < 4; it++) {
            int idx = tid + it * 256;
            int k = idx & 15, m = idx >> 4;
            As[k][m] = A[(size_t)(m0 + m) * lda + k0 + k];
        }
#pragma unroll
        for (int it = 0; it < 4; it++) {
            int idx = tid + it * 256;
            int k = idx & 15, n = idx >> 4;
            Bs[k][n] = B[(size_t)(n0 + n) * ldb + k0 + k];
        }
        __syncthreads();
#pragma unroll
        for (int k = 0; k < 16; k++) {
            float4 a = *(const float4*)&As[k][ty * 4];
            float4 b = *(const float4*)&Bs[k][tx * 4];
            float av[4] = {a.x, a.y, a.z, a.w};
            float bv[4] = {b.x, b.y, b.z, b.w};
#pragma unroll
            for (int i = 0; i < 4; i++)
#pragma unroll
                for (int j = 0; j < 4; j++) acc[i][j] = fmaf(av[i], bv[j], acc[i][j]);
        }
        __syncthreads();
    }

#pragma unroll
    for (int i = 0; i < 4; i++) {
        int m = m0 + ty * 4 + i;
#pragma unroll
        for (int j = 0; j < 4; j++) {
            int n = n0 + tx * 4 + j;
            C[(size_t)m * ldc + n] = alpha * acc[i][j];
        }
    }
}

// ------- fused softmax (4 heads per row) + head-mean + W2->bf16 -------------
__global__ __launch_bounds__(256) void softmax_fused(
    const float* __restrict__ W2, float* __restrict__ out)
{
    int row = blockIdx.x, tid = threadIdx.x;
    __shared__ float red[8];
    __shared__ float red2[8];
    float acc[4] = {0.f, 0.f, 0.f, 0.f};

#pragma unroll
    for (int h = 0; h < 4; h++) {
        float* p = g_scores + (size_t)h * 1048576 + (size_t)row * 1024;
        float v[4];
        float mx = -1e30f;
#pragma unroll
        for (int i = 0; i < 4; i++) { v[i] = p[tid + i * 256]; mx = fmaxf(mx, v[i]); }
#pragma unroll
        for (int o = 16; o; o >>= 1) mx = fmaxf(mx, __shfl_xor_sync(0xffffffffu, mx, o));
        __syncthreads();   // protect red reuse across h
        if ((tid & 31) == 0) red[tid >> 5] = mx;
        __syncthreads();
        float m2 = red[0];
#pragma unroll
        for (int w = 1; w < 8; w++) m2 = fmaxf(m2, red[w]);

        float s = 0.f;
#pragma unroll
        for (int i = 0; i < 4; i++) { v[i] = expf(v[i] - m2); s += v[i]; }
#pragma unroll
        for (int o = 16; o; o >>= 1) s += __shfl_xor_sync(0xffffffffu, s, o);
        if ((tid & 31) == 0) red2[tid >> 5] = s;
        __syncthreads();
        float tot = 0.f;
#pragma unroll
        for (int w = 0; w < 8; w++) tot += red2[w];
        float inv = 1.f / tot;
#pragma unroll
        for (int i = 0; i < 4; i++) {
            float pv = v[i] * inv;
            p[tid + i * 256] = pv;
            acc[i] += pv;
        }
    }
#pragma unroll
    for (int i = 0; i < 4; i++)
        out[(size_t)row * 1024 + tid + i * 256] = 0.25f * acc[i];
    if (row < 128) g_W2bf[row * 256 + tid] = __float2bfloat16(W2[row * 256 + tid]);
}

// ------- dedicated ctx kernel: g_ctxp[kc] partial of P @ V ------------------
// grid (4 kchunks, 16 qtiles, 4 heads), 256 thr. Per CTA: K=256 in 2 sub-chunks.
// Warp w -> q rows w*8..+8, lane = d. VsT stride 132 -> conflict-free LDS.128.
__global__ __launch_bounds__(256) void ctx_kernel()
{
    extern __shared__ float cs[];
    float* Pt = cs;                 // 64 x 132
    float* VsT = cs + 64 * 132;     // 32 x 132
    int tid = threadIdx.x;
    int kc = blockIdx.x;
    int q0 = blockIdx.y * 64;
    int h  = blockIdx.z;
    int lane = tid & 31, wid = tid >> 5;
    int qb = wid * 8;
    float acc[8];
#pragma unroll
    for (int i = 0; i < 8; i++) acc[i] = 0.f;

    const float* Pg = g_scores + (size_t)h * 1048576;
    const float* Vg = g_qkv + 256 + h * 32;

#pragma unroll
    for (int sub = 0; sub < 2; sub++) {
        int k0 = kc * 256 + sub * 128;
        // stage P 64 x 128 (float4, coalesced; conflict-free STS)
#pragma unroll
        for (int j = 0; j < 8; j++) {
            int idx = tid + j * 256;
            int r = idx >> 5, c4 = idx & 31;
            float4 v = *(const float4*)&Pg[(size_t)(q0 + r) * 1024 + k0 + c4 * 4];
            *(float4*)&Pt[r * 132 + c4 * 4] = v;
        }
        // stage V transposed: VsT[d][k] (coalesced LDG)
#pragma unroll
        for (int j = 0; j < 16; j++) {
            int idx = tid + j * 256;
            int k = idx >> 5, d = idx & 31;
            VsT[d * 132 + k] = Vg[(size_t)(k0 + k) * 384 + d];
        }
        __syncthreads();
#pragma unroll
        for (int kb = 0; kb < 32; kb++) {
            float4 v = *(const float4*)&VsT[lane * 132 + kb * 4];
#pragma unroll
            for (int q = 0; q < 8; q++) {
                float4 p = *(const float4*)&Pt[(qb + q) * 132 + kb * 4];
                acc[q] = fmaf(p.x, v.x, acc[q]);
                acc[q] = fmaf(p.y, v.y, acc[q]);
                acc[q] = fmaf(p.z, v.z, acc[q]);
                acc[q] = fmaf(p.w, v.w, acc[q]);
            }
        }
        __syncthreads();
    }
    float* outp = g_ctxp[kc];
#pragma unroll
    for (int q = 0; q < 8; q++)
        outp[(size_t)(q0 + qb + q) * 128 + h * 32 + lane] = acc[q];
}

// ------- fused attended-projection + n1 + bf16 convert ----------------------
// grid (4,16): each CTA computes att rows [by*64,+64) x 128 (x-redundant),
// summing the 4 ctx split-K partials while staging; bx==0 writes g_att;
// then computes n1bf chunk [by*64,+64) x [bx*64,+64).
__global__ __launch_bounds__(256) void att_n1(
    const float* __restrict__ outw, const float* __restrict__ outb,
    const float* __restrict__ W1)
{
    __shared__ float As[16][68];
    __shared__ float Bs[16][132];
    __shared__ float att_s[64][133];
    int tid = threadIdx.x, tx = tid & 15, ty = tid >> 4;
    int m0 = blockIdx.y * 64, n0 = blockIdx.x * 64;

    // ---- phase 1: att = ctx @ outw^T + outb, 64 x 128 ----
    float a8[4][8];
#pragma unroll
    for (int i = 0; i < 4; i++)
#pragma unroll
        for (int j = 0; j < 8; j++) a8[i][j] = 0.f;

    for (int k0 = 0; k0 < 128; k0 += 16) {
#pragma unroll
        for (int it = 0; it < 4; it++) {
            int idx = tid + it * 256;
            size_t o = (size_t)(m0 + (idx >> 4)) * 128 + k0 + (idx & 15);
            As[idx & 15][idx >> 4] = g_ctxp[0][o] + g_ctxp[1][o] + g_ctxp[2][o] + g_ctxp[3][o];
        }
#pragma unroll
        for (int it = 0; it < 8; it++) {
            int idx = tid + it * 256;
            int n = idx & 127, k = idx >> 7;
            Bs[k][n] = outw[(size_t)n * 128 + k0 + k];
        }
        __syncthreads();
#pragma unroll
        for (int k = 0; k < 16; k++) {
            float4 a = *(const float4*)&As[k][ty * 4];
            float4 b0 = *(const float4*)&Bs[k][tx * 8];
            float4 b1 = *(const float4*)&Bs[k][tx * 8 + 4];
            float av[4] = {a.x, a.y, a.z, a.w};
            float bv[8] = {b0.x, b0.y, b0.z, b0.w, b1.x, b1.y, b1.z, b1.w};
#pragma unroll
            for (int i = 0; i < 4; i++)
#pragma unroll
                for (int j = 0; j < 8; j++) a8[i][j] = fmaf(av[i], bv[j], a8[i][j]);
        }
        __syncthreads();
    }
#pragma unroll
    for (int i = 0; i < 4; i++) {
        int m = ty * 4 + i;
#pragma unroll
        for (int j = 0; j < 8; j++) {
            int col = tx * 8 + j;
            float v = a8[i][j] + outb[col];
            att_s[m][col] = v;
            if (blockIdx.x == 0) g_att[(size_t)(m0 + m) * 128 + col] = v;
        }
    }
    __syncthreads();

    // ---- phase 2: n1 = att @ W1[:,128:]^T, 64 x 64 chunk -> bf16 ----
    float c2[4][4];
#pragma unroll
    for (int i = 0; i < 4; i++)
#pragma unroll
        for (int j = 0; j < 4; j++) c2[i][j] = 0.f;

    for (int k0 = 0; k0 < 128; k0 += 16) {
#pragma unroll
        for (int it = 0; it < 4; it++) {
            int idx = tid + it * 256;
            As[idx & 15][idx >> 4] = W1[(size_t)(n0 + (idx >> 4)) * 256 + 128 + k0 + (idx & 15)];
        }
        __syncthreads();
#pragma unroll
        for (int k = 0; k < 16; k++) {
            float4 b = *(const float4*)&As[k][tx * 4];
            float bv[4] = {b.x, b.y, b.z, b.w};
#pragma unroll
            for (int i = 0; i < 4; i++) {
                float av = att_s[ty * 4 + i][k0 + k];
#pragma unroll
                for (int j = 0; j < 4; j++) c2[i][j] = fmaf(av, bv[j], c2[i][j]);
            }
        }
        __syncthreads();
    }
#pragma unroll
    for (int i = 0; i < 4; i++) {
        int m = m0 + ty * 4 + i;
        __nv_bfloat162 lo = __floats2bfloat162_rn(c2[i][0], c2[i][1]);
        __nv_bfloat162 hi = __floats2bfloat162_rn(c2[i][2], c2[i][3]);
        *(uint32_t*)&g_n1bf[(size_t)m * 256 + n0 + tx * 4] = *(uint32_t*)&lo;
        *(uint32_t*)&g_n1bf[(size_t)m * 256 + n0 + tx * 4 + 2] = *(uint32_t*)&hi;
    }
}

// ---------------- coordination head ----------------------------------------
__global__ __launch_bounds__(256) void coord_kernel(
    const float* __restrict__ Wc1, const float* __restrict__ bc1,
    const float* __restrict__ Wc2, const float* __restrict__ bc2,
    float* __restrict__ out)
{
    __shared__ float ps[256];
    __shared__ float gs[128];
    __shared__ float h[256];
    int tid = threadIdx.x;
    int d = tid & 127, half = tid >> 7;
    float s = 0.f;
    for (int r = half * 512; r < half * 512 + 512; r++) s += g_att[r * 128 + d];
    ps[tid] = s;
    __syncthreads();
    if (tid < 128) gs[tid] = (ps[tid] + ps[tid + 128]) * (1.f / 1024.f);
    __syncthreads();
    float hv = bc1[tid];
    for (int c = 0; c < 128; c++) hv = fmaf(gs[c], Wc1[tid * 128 + c], hv);
    h[tid] = fmaxf(hv, 0.f);
    __syncthreads();
    if (tid < 32) {
        float z = bc2[tid];
        for (int c = 0; c < 256; c++) z = fmaf(h[c], Wc2[tid * 256 + c], z);
        out[tid] = z;
    }
}

// ============== persistent pairwise MLP (34.4 GMAC, bf16 mma.sync) ==========
#define GRID_MATCH 152
#define NTILES 8192

#define SM_A 0
#define SM_B 67584
#define SM_T1_0 135168
#define SM_T1_1 143360
#define SM_N1_0 151552
#define SM_N1_1 160256
#define SM_W3 168960
#define SM_B2 169472
#define SM_ZP 169984
#define SMEM_TOTAL 171008
#define ROWSTRIDE_B 528
#define N1STRIDE 528

__device__ __forceinline__ void ldm_x4(uint32_t& r0, uint32_t& r1, uint32_t& r2, uint32_t& r3,
                                       uint32_t addr)
{
    asm volatile("ldmatrix.sync.aligned.m8n8.x4.shared.b16 {%0,%1,%2,%3}, [%4];"
                 : "=r"(r0), "=r"(r1), "=r"(r2), "=r"(r3)
                 : "r"(addr));
}

__device__ __forceinline__ void mma_bf16(float& c0, float& c1, float& c2, float& c3,
                                         uint32_t a0, uint32_t a1, uint32_t a2, uint32_t a3,
                                         uint32_t b0, uint32_t b1)
{
    asm volatile(
        "mma.sync.aligned.m16n8k16.row.col.f32.bf16.bf16.f32 "
        "{%0,%1,%2,%3}, {%4,%5,%6,%7}, {%8,%9}, {%0,%1,%2,%3};"
        : "+f"(c0), "+f"(c1), "+f"(c2), "+f"(c3)
        : "r"(a0), "r"(a1), "r"(a2), "r"(a3), "r"(b0), "r"(b1));
}

__device__ __forceinline__ uint32_t rp2(float a, float b, uint32_t nv)
{
    __nv_bfloat162 n = *reinterpret_cast<const __nv_bfloat162*>(&nv);
    float x0 = a + __bfloat162float(n.x);
    float x1 = b + __bfloat162float(n.y);
    __nv_bfloat162 o = __floats2bfloat162_rn(fmaxf(x0, 0.f), fmaxf(x1, 0.f));
    return *reinterpret_cast<uint32_t*>(&o);
}

__device__ __forceinline__ void cp16(uint32_t dst, const void* src)
{
    asm volatile("cp.async.cg.shared.global [%0], [%1], 16;" :: "r"(dst), "l"(src));
}
#define CP_COMMIT() asm volatile("cp.async.commit_group;" ::: "memory")
#define CP_WAIT0()  asm volatile("cp.async.wait_group 0;" ::: "memory")

__global__ __launch_bounds__(256, 1) void match_kernel(
    const float* __restrict__ W3, const float* __restrict__ b2v,
    const float* __restrict__ b3, float* __restrict__ out)
{
    extern __shared__ char sm[];
    float* sW3 = (float*)(sm + SM_W3);
    float* sb2 = (float*)(sm + SM_B2);
    float* zpart = (float*)(sm + SM_ZP);

    int tid = threadIdx.x;
    int lane = tid & 31, wid = tid >> 5;
    int wm = wid >> 1, wn = wid & 1;

    const int t1Off[2] = {SM_T1_0, SM_T1_1};
    const int n1Off[2] = {SM_N1_0, SM_N1_1};
    uint32_t smuBase = (uint32_t)__cvta_generic_to_shared(sm);

    {
        const uint4* bsrc = (const uint4*)g_W2bf;
#pragma unroll
        for (int j = 0; j < 16; j++) {
            int i = tid + j * 256;
            int r = i >> 5, q = i & 31;
            *(uint4*)(sm + SM_B + r * ROWSTRIDE_B + q * 16) = bsrc[i];
        }
        if (tid < 128) { sW3[tid] = W3[tid]; sb2[tid] = b2v[tid]; }
    }
    float b3v = b3[0];

    uint32_t aSm = (uint32_t)__cvta_generic_to_shared(sm + SM_A);
    uint32_t bSm = (uint32_t)__cvta_generic_to_shared(sm + SM_B);

    uint32_t aBase[2];
#pragma unroll
    for (int mt = 0; mt < 2; mt++) {
        int row = wm * 32 + mt * 16 + (lane & 15);
        int colb = ((lane >> 4) << 3) * 2;
        aBase[mt] = aSm + row * ROWSTRIDE_B + colb;
    }
    uint32_t bBase[4];
#pragma unroll
    for (int nt2 = 0; nt2 < 4; nt2++) {
        int nrow = wn * 64 + nt2 * 16 + ((lane >> 4) << 3) + (lane & 7);
        int kb = (((lane >> 3) & 1) << 3) * 2;
        bBase[nt2] = bSm + nrow * ROWSTRIDE_B + kb;
    }
    __syncthreads();

    int firstTile = blockIdx.x;
    if (firstTile < NTILES) {
        int t0 = (firstTile >> 6) * 8, n0 = (firstTile & 63) * 16;
        const float4* ts = (const float4*)(g_t1 + (size_t)t0 * 256);
        const uint4* ns = (const uint4*)(g_n1bf + (size_t)n0 * 256);
        cp16(smuBase + SM_T1_0 + tid * 16, ts + tid);
        cp16(smuBase + SM_T1_0 + (tid + 256) * 16, ts + tid + 256);
        {
            int i0 = tid, i1 = tid + 256;
            cp16(smuBase + SM_N1_0 + (i0 >> 5) * N1STRIDE + (i0 & 31) * 16, ns + i0);
            cp16(smuBase + SM_N1_0 + (i1 >> 5) * N1STRIDE + (i1 & 31) * 16, ns + i1);
        }
        CP_COMMIT();
    }

    int bi = 0;
    for (int tile = firstTile; tile < NTILES; tile += GRID_MATCH, bi ^= 1) {
        int n0 = (tile & 63) * 16, t0 = (tile >> 6) * 8;

        CP_WAIT0();
        __syncthreads();

        {
            const float4* t1f4 = (const float4*)(sm + t1Off[bi]);
            const char* n1b = sm + n1Off[bi];
            int r = tid & 127, qp = tid >> 7;
            int tl = r >> 4, nl = r & 15;
            const char* n1row = n1b + nl * N1STRIDE;
            char* aRow = sm + SM_A + r * ROWSTRIDE_B;
            const float4* t1row = t1f4 + tl * 64;
#pragma unroll
            for (int j = 0; j < 16; j++) {
                int q = qp + 2 * j;
                float4 ta = t1row[q * 2];
                float4 tb = t1row[q * 2 + 1];
                uint4 nv = *(const uint4*)(n1row + q * 16);
                uint4 o;
                o.x = rp2(ta.x, ta.y, nv.x);
                o.y = rp2(ta.z, ta.w, nv.y);
                o.z = rp2(tb.x, tb.y, nv.z);
                o.w = rp2(tb.z, tb.w, nv.w);
                *(uint4*)(aRow + q * 16) = o;
            }
        }
        __syncthreads();

        int nextTile = tile + GRID_MATCH;
        if (nextTile < NTILES) {
            int nt0 = (nextTile >> 6) * 8, nn0 = (nextTile & 63) * 16;
            const float4* ts = (const float4*)(g_t1 + (size_t)nt0 * 256);
            const uint4* ns = (const uint4*)(g_n1bf + (size_t)nn0 * 256);
            int tb = t1Off[bi ^ 1], nb = n1Off[bi ^ 1];
            cp16(smuBase + tb + tid * 16, ts + tid);
            cp16(smuBase + tb + (tid + 256) * 16, ts + tid + 256);
            int i0 = tid, i1 = tid + 256;
            cp16(smuBase + nb + (i0 >> 5) * N1STRIDE + (i0 & 31) * 16, ns + i0);
            cp16(smuBase + nb + (i1 >> 5) * N1STRIDE + (i1 & 31) * 16, ns + i1);
        }
        CP_COMMIT();

        float c[2][8][4];
#pragma unroll
        for (int mt = 0; mt < 2; mt++)
#pragma unroll
            for (int nt = 0; nt < 8; nt++)
#pragma unroll
                for (int j = 0; j < 4; j++) c[mt][nt][j] = 0.f;

        uint32_t a[2][2][4];
        uint32_t b[2][8][2];
#pragma unroll
        for (int mt = 0; mt < 2; mt++)
            ldm_x4(a[0][mt][0], a[0][mt][1], a[0][mt][2], a[0][mt][3], aBase[mt]);
#pragma unroll
        for (int nt2 = 0; nt2 < 4; nt2++) {
            uint32_t r0, r1, r2, r3;
            ldm_x4(r0, r1, r2, r3, bBase[nt2]);
            b[0][2 * nt2][0] = r0; b[0][2 * nt2][1] = r1;
            b[0][2 * nt2 + 1][0] = r2; b[0][2 * nt2 + 1][1] = r3;
        }

#pragma unroll
        for (int kk = 0; kk < 16; kk++) {
            int cur = kk & 1, nxt = cur ^ 1;
            if (kk < 15) {
                int ko = (kk + 1) * 32;
#pragma unroll
                for (int mt = 0; mt < 2; mt++)
                    ldm_x4(a[nxt][mt][0], a[nxt][mt][1], a[nxt][mt][2], a[nxt][mt][3],
                           aBase[mt] + ko);
#pragma unroll
                for (int nt2 = 0; nt2 < 4; nt2++) {
                    uint32_t r0, r1, r2, r3;
                    ldm_x4(r0, r1, r2, r3, bBase[nt2] + ko);
                    b[nxt][2 * nt2][0] = r0; b[nxt][2 * nt2][1] = r1;
                    b[nxt][2 * nt2 + 1][0] = r2; b[nxt][2 * nt2 + 1][1] = r3;
                }
            }
#pragma unroll
            for (int mt = 0; mt < 2; mt++)
#pragma unroll
                for (int nt = 0; nt < 8; nt++)
                    mma_bf16(c[mt][nt][0], c[mt][nt][1], c[mt][nt][2], c[mt][nt][3],
                             a[cur][mt][0], a[cur][mt][1], a[cur][mt][2], a[cur][mt][3],
                             b[cur][nt][0], b[cur][nt][1]);
        }

        int g = lane >> 2, q = lane & 3;
#pragma unroll
        for (int mt = 0; mt < 2; mt++) {
            float p0 = 0.f, p1 = 0.f;
#pragma unroll
            for (int nt = 0; nt < 8; nt++) {
                int col = wn * 64 + nt * 8 + q * 2;
                float w0 = sW3[col], w1 = sW3[col + 1];
                float bb0 = sb2[col], bb1 = sb2[col + 1];
                p0 += fmaxf(c[mt][nt][0] + bb0, 0.f) * w0 + fmaxf(c[mt][nt][1] + bb1, 0.f) * w1;
                p1 += fmaxf(c[mt][nt][2] + bb0, 0.f) * w0 + fmaxf(c[mt][nt][3] + bb1, 0.f) * w1;
            }
            p0 += __shfl_xor_sync(0xffffffffu, p0, 1);
            p0 += __shfl_xor_sync(0xffffffffu, p0, 2);
            p1 += __shfl_xor_sync(0xffffffffu, p1, 1);
            p1 += __shfl_xor_sync(0xffffffffu, p1, 2);
            if (q == 0) {
                int rA = wm * 32 + mt * 16 + g;
                zpart[rA * 2 + wn] = p0;
                zpart[(rA + 8) * 2 + wn] = p1;
            }
        }
        __syncthreads();
        if (tid < 128) {
            float z = zpart[tid * 2] + zpart[tid * 2 + 1] + b3v;
            float s = 1.f / (1.f + expf(-z));
            int t = t0 + (tid >> 4), n = n0 + (tid & 15);
            out[(size_t)t * 1024 + n] = s;
        }
        __syncthreads();
    }
}

// ---------------- launch ---------------------------------------------------
extern "C" void kernel_launch(void* const* d_in, const int* in_sizes, int n_in,
                              void* d_out, int out_size)
{
    const float* node = (const float*)d_in[0];
    const float* task = (const float*)d_in[1];
    const float* ipw  = (const float*)d_in[2];
    const float* ipb  = (const float*)d_in[3];
    const float* outw = (const float*)d_in[4];
    const float* outb = (const float*)d_in[5];
    const float* W1   = (const float*)d_in[6];
    const float* b1   = (const float*)d_in[7];
    const float* W2   = (const float*)d_in[8];
    const float* b2   = (const float*)d_in[9];
    const float* W3   = (const float*)d_in[10];
    const float* b3   = (const float*)d_in[11];
    const float* Wc1  = (const float*)d_in[12];
    const float* bc1  = (const float*)d_in[13];
    const float* Wc2  = (const float*)d_in[14];
    const float* bc2  = (const float*)d_in[15];
    float* out = (float*)d_out;

    float *qkv, *scores;
    cudaGetSymbolAddress((void**)&qkv, g_qkv);
    cudaGetSymbolAddress((void**)&scores, g_scores);

    // 0: QKV + t1 fused
    qkv_t1_kernel<<<dim3(6, 16, 2), 256>>>(node, ipw, ipb, task, W1, b1);
    // 1: scores (all 4 heads)
    gemm_f32b<<<dim3(16, 16, 4), 256>>>(qkv, 384, 32, qkv + 128, 384, 32,
                                        0.17677669529663687f, scores, 1024, 1048576, 32);
    // 2: softmax + head-mean + W2->bf16
    softmax_fused<<<1024, 256>>>(W2, out + 1048608);
    // 3: ctx partials (deterministic split-K, dedicated kernel)
    cudaFuncSetAttribute(ctx_kernel, cudaFuncAttributeMaxDynamicSharedMemorySize, 50688);
    ctx_kernel<<<dim3(4, 16, 4), 256, 50688>>>();
    // 4: attended projection (sums partials) + n1 (bf16) fused
    att_n1<<<dim3(4, 16), 256>>>(outw, outb, W1);
    // 5: persistent bf16 HMMA pairwise MLP
    cudaFuncSetAttribute(match_kernel, cudaFuncAttributeMaxDynamicSharedMemorySize, SMEM_TOTAL);
    match_kernel<<<GRID_MATCH, 256, SMEM_TOTAL>>>(W3, b2, b3, out);
    // 6: coordination head
    coord_kernel<<<1, 256>>>(Wc1, bc1, Wc2, bc2, out + 1048576);
}

// round 16
// speedup vs baseline: 2.8446x; 1.0060x over previous
#include <cuda_runtime.h>
#include <cuda_bf16.h>
#include <math.h>
#include <stdint.h>

#define NQ 1024
#define TT 1024
#define DM 128
#define CH 256
#define KO 128

// ---------------- scratch (static device memory; no allocs) ----------------
__device__ float g_qkv[NQ * 384];
__device__ float g_t1[TT * CH];
__device__ float g_scores[4 * NQ * NQ];
__device__ float g_ctxp[8][NQ * DM];   // split-K partials (deterministic)
__device__ float g_att[NQ * DM];
__device__ __nv_bfloat16 g_n1bf[NQ * CH];
__device__ __nv_bfloat16 g_W2bf[KO * CH];

// ---------------- fused QKV + t1 projections (z selects problem) -----------
__global__ __launch_bounds__(256) void qkv_t1_kernel(
    const float* __restrict__ node, const float* __restrict__ ipw, const float* __restrict__ ipb,
    const float* __restrict__ task, const float* __restrict__ W1, const float* __restrict__ b1)
{
    __shared__ float As[16][68];
    __shared__ float Bs[16][68];
    const float *A, *B, *bias;
    float* C;
    int ldb, ldc;
    if (blockIdx.z == 0) { A = node; B = ipw; bias = ipb; C = g_qkv; ldb = 128; ldc = 384; }
    else { if (blockIdx.x >= 4) return;
           A = task; B = W1; bias = b1; C = g_t1; ldb = 256; ldc = 256; }
    int tid = threadIdx.x, tx = tid & 15, ty = tid >> 4;
    int m0 = blockIdx.y * 64, n0 = blockIdx.x * 64;

    float acc[4][4];
#pragma unroll
    for (int i = 0; i < 4; i++)
#pragma unroll
        for (int j = 0; j < 4; j++) acc[i][j] = 0.f;

    for (int k0 = 0; k0 < 128; k0 += 16) {
#pragma unroll
        for (int it = 0; it < 4; it++) {
            int idx = tid + it * 256;
            As[idx & 15][idx >> 4] = A[(size_t)(m0 + (idx >> 4)) * 128 + k0 + (idx & 15)];
        }
#pragma unroll
        for (int it = 0; it < 4; it++) {
            int idx = tid + it * 256;
            Bs[idx & 15][idx >> 4] = B[(size_t)(n0 + (idx >> 4)) * ldb + k0 + (idx & 15)];
        }
        __syncthreads();
#pragma unroll
        for (int k = 0; k < 16; k++) {
            float4 a = *(const float4*)&As[k][ty * 4];
            float4 b = *(const float4*)&Bs[k][tx * 4];
            float av[4] = {a.x, a.y, a.z, a.w};
            float bv[4] = {b.x, b.y, b.z, b.w};
#pragma unroll
            for (int i = 0; i < 4; i++)
#pragma unroll
                for (int j = 0; j < 4; j++) acc[i][j] = fmaf(av[i], bv[j], acc[i][j]);
        }
        __syncthreads();
    }
#pragma unroll
    for (int i = 0; i < 4; i++)
#pragma unroll
        for (int j = 0; j < 4; j++) {
            int n = n0 + tx * 4 + j;
            C[(size_t)(m0 + ty * 4 + i) * ldc + n] = acc[i][j] + bias[n];
        }
}

// ---------------- scores GEMM (batched over heads) --------------------------
__global__ __launch_bounds__(256) void gemm_f32b(
    const float* __restrict__ A, int lda, int sAz,
    const float* __restrict__ B, int ldb, int sBz,
    float alpha, float* __restrict__ C, int ldc, int sCz, int K)
{
    __shared__ float As[16][68];
    __shared__ float Bs[16][68];
    int tid = threadIdx.x;
    int tx = tid & 15, ty = tid >> 4;
    int m0 = blockIdx.y * 64, n0 = blockIdx.x * 64;
    int h = blockIdx.z;
    A += (size_t)h * sAz; B += (size_t)h * sBz; C += (size_t)h * sCz;

    float acc[4][4];
#pragma unroll
    for (int i = 0; i < 4; i++)
#pragma unroll
        for (int j = 0; j < 4; j++) acc[i][j] = 0.f;

    for (int k0 = 0; k0 < K; k0 += 16) {
#pragma unroll
        for (int it = 0; it < 4; it++) {
            int idx = tid + it * 256;
            int k = idx & 15, m = idx >> 4;
            As[k][m] = A[(size_t)(m0 + m) * lda + k0 + k];
        }
#pragma unroll
        for (int it = 0; it < 4; it++) {
            int idx = tid + it * 256;
            int k = idx & 15, n = idx >> 4;
            Bs[k][n] = B[(size_t)(n0 + n) * ldb + k0 + k];
        }
        __syncthreads();
#pragma unroll
        for (int k = 0; k < 16; k++) {
            float4 a = *(const float4*)&As[k][ty * 4];
            float4 b = *(const float4*)&Bs[k][tx * 4];
            float av[4] = {a.x, a.y, a.z, a.w};
            float bv[4] = {b.x, b.y, b.z, b.w};
#pragma unroll
            for (int i = 0; i < 4; i++)
#pragma unroll
                for (int j = 0; j < 4; j++) acc[i][j] = fmaf(av[i], bv[j], acc[i][j]);
        }
        __syncthreads();
    }

#pragma unroll
    for (int i = 0; i < 4; i++) {
        int m = m0 + ty * 4 + i;
#pragma unroll
        for (int j = 0; j < 4; j++) {
            int n = n0 + tx * 4 + j;
            C[(size_t)m * ldc + n] = alpha * acc[i][j];
        }
    }
}

// ------- fused softmax (4 heads per row) + head-mean + W2->bf16 -------------
__global__ __launch_bounds__(256) void softmax_fused(
    const float* __restrict__ W2, float* __restrict__ out)
{
    int row = blockIdx.x, tid = threadIdx.x;
    __shared__ float red[8];
    __shared__ float red2[8];
    float acc[4] = {0.f, 0.f, 0.f, 0.f};

#pragma unroll
    for (int h = 0; h < 4; h++) {
        float* p = g_scores + (size_t)h * 1048576 + (size_t)row * 1024;
        float v[4];
        float mx = -1e30f;
#pragma unroll
        for (int i = 0; i < 4; i++) { v[i] = p[tid + i * 256]; mx = fmaxf(mx, v[i]); }
#pragma unroll
        for (int o = 16; o; o >>= 1) mx = fmaxf(mx, __shfl_xor_sync(0xffffffffu, mx, o));
        __syncthreads();   // protect red reuse across h
        if ((tid & 31) == 0) red[tid >> 5] = mx;
        __syncthreads();
        float m2 = red[0];
#pragma unroll
        for (int w = 1; w < 8; w++) m2 = fmaxf(m2, red[w]);

        float s = 0.f;
#pragma unroll
        for (int i = 0; i < 4; i++) { v[i] = expf(v[i] - m2); s += v[i]; }
#pragma unroll
        for (int o = 16; o; o >>= 1) s += __shfl_xor_sync(0xffffffffu, s, o);
        if ((tid & 31) == 0) red2[tid >> 5] = s;
        __syncthreads();
        float tot = 0.f;
#pragma unroll
        for (int w = 0; w < 8; w++) tot += red2[w];
        float inv = 1.f / tot;
#pragma unroll
        for (int i = 0; i < 4; i++) {
            float pv = v[i] * inv;
            p[tid + i * 256] = pv;
            acc[i] += pv;
        }
    }
#pragma unroll
    for (int i = 0; i < 4; i++)
        out[(size_t)row * 1024 + tid + i * 256] = 0.25f * acc[i];
    if (row < 128) g_W2bf[row * 256 + tid] = __float2bfloat16(W2[row * 256 + tid]);
}

// ------- dedicated ctx kernel: g_ctxp[kc] partial of P @ V ------------------
// grid (8 kchunks, 16 qtiles, 4 heads) = 512 CTAs (~3.4/SM). K=128 per CTA.
// Warp w -> q rows w*8..+8, lane = d. P loads broadcast; VsT stride 132.
__global__ __launch_bounds__(256) void ctx_kernel()
{
    extern __shared__ float cs[];
    float* Pt = cs;                 // 64 x 132
    float* VsT = cs + 64 * 132;     // 32 x 132
    int tid = threadIdx.x;
    int kc = blockIdx.x;
    int q0 = blockIdx.y * 64;
    int h  = blockIdx.z;
    int lane = tid & 31, wid = tid >> 5;
    int qb = wid * 8;
    int k0 = kc * 128;
    float acc[8];
#pragma unroll
    for (int i = 0; i < 8; i++) acc[i] = 0.f;

    const float* Pg = g_scores + (size_t)h * 1048576;
    const float* Vg = g_qkv + 256 + h * 32;

    // stage P 64 x 128 (float4, coalesced)
#pragma unroll
    for (int j = 0; j < 8; j++) {
        int idx = tid + j * 256;
        int r = idx >> 5, c4 = idx & 31;
        float4 v = *(const float4*)&Pg[(size_t)(q0 + r) * 1024 + k0 + c4 * 4];
        *(float4*)&Pt[r * 132 + c4 * 4] = v;
    }
    // stage V transposed: VsT[d][k]
#pragma unroll
    for (int j = 0; j < 16; j++) {
        int idx = tid + j * 256;
        int k = idx >> 5, d = idx & 31;
        VsT[d * 132 + k] = Vg[(size_t)(k0 + k) * 384 + d];
    }
    __syncthreads();
#pragma unroll
    for (int kb = 0; kb < 32; kb++) {
        float4 v = *(const float4*)&VsT[lane * 132 + kb * 4];
#pragma unroll
        for (int q = 0; q < 8; q++) {
            float4 p = *(const float4*)&Pt[(qb + q) * 132 + kb * 4];
            acc[q] = fmaf(p.x, v.x, acc[q]);
            acc[q] = fmaf(p.y, v.y, acc[q]);
            acc[q] = fmaf(p.z, v.z, acc[q]);
            acc[q] = fmaf(p.w, v.w, acc[q]);
        }
    }
    float* outp = g_ctxp[kc];
#pragma unroll
    for (int q = 0; q < 8; q++)
        outp[(size_t)(q0 + qb + q) * 128 + h * 32 + lane] = acc[q];
}

// ------- fused attended-projection + n1 + bf16 convert ----------------------
__global__ __launch_bounds__(256) void att_n1(
    const float* __restrict__ outw, const float* __restrict__ outb,
    const float* __restrict__ W1)
{
    __shared__ float As[16][68];
    __shared__ float Bs[16][132];
    __shared__ float att_s[64][133];
    int tid = threadIdx.x, tx = tid & 15, ty = tid >> 4;
    int m0 = blockIdx.y * 64, n0 = blockIdx.x * 64;

    // ---- phase 1: att = ctx @ outw^T + outb, 64 x 128 ----
    float a8[4][8];
#pragma unroll
    for (int i = 0; i < 4; i++)
#pragma unroll
        for (int j = 0; j < 8; j++) a8[i][j] = 0.f;

    for (int k0 = 0; k0 < 128; k0 += 16) {
#pragma unroll
        for (int it = 0; it < 4; it++) {
            int idx = tid + it * 256;
            size_t o = (size_t)(m0 + (idx >> 4)) * 128 + k0 + (idx & 15);
            float sum = 0.f;
#pragma unroll
            for (int kc = 0; kc < 8; kc++) sum += g_ctxp[kc][o];
            As[idx & 15][idx >> 4] = sum;
        }
#pragma unroll
        for (int it = 0; it < 8; it++) {
            int idx = tid + it * 256;
            int n = idx & 127, k = idx >> 7;
            Bs[k][n] = outw[(size_t)n * 128 + k0 + k];
        }
        __syncthreads();
#pragma unroll
        for (int k = 0; k < 16; k++) {
            float4 a = *(const float4*)&As[k][ty * 4];
            float4 b0 = *(const float4*)&Bs[k][tx * 8];
            float4 b1 = *(const float4*)&Bs[k][tx * 8 + 4];
            float av[4] = {a.x, a.y, a.z, a.w};
            float bv[8] = {b0.x, b0.y, b0.z, b0.w, b1.x, b1.y, b1.z, b1.w};
#pragma unroll
            for (int i = 0; i < 4; i++)
#pragma unroll
                for (int j = 0; j < 8; j++) a8[i][j] = fmaf(av[i], bv[j], a8[i][j]);
        }
        __syncthreads();
    }
#pragma unroll
    for (int i = 0; i < 4; i++) {
        int m = ty * 4 + i;
#pragma unroll
        for (int j = 0; j < 8; j++) {
            int col = tx * 8 + j;
            float v = a8[i][j] + outb[col];
            att_s[m][col] = v;
            if (blockIdx.x == 0) g_att[(size_t)(m0 + m) * 128 + col] = v;
        }
    }
    __syncthreads();

    // ---- phase 2: n1 = att @ W1[:,128:]^T, 64 x 64 chunk -> bf16 ----
    float c2[4][4];
#pragma unroll
    for (int i = 0; i < 4; i++)
#pragma unroll
        for (int j = 0; j < 4; j++) c2[i][j] = 0.f;

    for (int k0 = 0; k0 < 128; k0 += 16) {
#pragma unroll
        for (int it = 0; it < 4; it++) {
            int idx = tid + it * 256;
            As[idx & 15][idx >> 4] = W1[(size_t)(n0 + (idx >> 4)) * 256 + 128 + k0 + (idx & 15)];
        }
        __syncthreads();
#pragma unroll
        for (int k = 0; k < 16; k++) {
            float4 b = *(const float4*)&As[k][tx * 4];
            float bv[4] = {b.x, b.y, b.z, b.w};
#pragma unroll
            for (int i = 0; i < 4; i++) {
                float av = att_s[ty * 4 + i][k0 + k];
#pragma unroll
                for (int j = 0; j < 4; j++) c2[i][j] = fmaf(av, bv[j], c2[i][j]);
            }
        }
        __syncthreads();
    }
#pragma unroll
    for (int i = 0; i < 4; i++) {
        int m = m0 + ty * 4 + i;
        __nv_bfloat162 lo = __floats2bfloat162_rn(c2[i][0], c2[i][1]);
        __nv_bfloat162 hi = __floats2bfloat162_rn(c2[i][2], c2[i][3]);
        *(uint32_t*)&g_n1bf[(size_t)m * 256 + n0 + tx * 4] = *(uint32_t*)&lo;
        *(uint32_t*)&g_n1bf[(size_t)m * 256 + n0 + tx * 4 + 2] = *(uint32_t*)&hi;
    }
}

// ============== persistent pairwise MLP (34.4 GMAC, bf16 mma.sync) ==========
// CTA GRID_MATCH-1 (a 53-tile CTA) also computes the coordination head first.
#define GRID_MATCH 152
#define NTILES 8192

#define SM_A 0
#define SM_B 67584
#define SM_T1_0 135168
#define SM_T1_1 143360
#define SM_N1_0 151552
#define SM_N1_1 160256
#define SM_W3 168960
#define SM_B2 169472
#define SM_ZP 169984
#define SMEM_TOTAL 171008
#define ROWSTRIDE_B 528
#define N1STRIDE 528

__device__ __forceinline__ void ldm_x4(uint32_t& r0, uint32_t& r1, uint32_t& r2, uint32_t& r3,
                                       uint32_t addr)
{
    asm volatile("ldmatrix.sync.aligned.m8n8.x4.shared.b16 {%0,%1,%2,%3}, [%4];"
                 : "=r"(r0), "=r"(r1), "=r"(r2), "=r"(r3)
                 : "r"(addr));
}

__device__ __forceinline__ void mma_bf16(float& c0, float& c1, float& c2, float& c3,
                                         uint32_t a0, uint32_t a1, uint32_t a2, uint32_t a3,
                                         uint32_t b0, uint32_t b1)
{
    asm volatile(
        "mma.sync.aligned.m16n8k16.row.col.f32.bf16.bf16.f32 "
        "{%0,%1,%2,%3}, {%4,%5,%6,%7}, {%8,%9}, {%0,%1,%2,%3};"
        : "+f"(c0), "+f"(c1), "+f"(c2), "+f"(c3)
        : "r"(a0), "r"(a1), "r"(a2), "r"(a3), "r"(b0), "r"(b1));
}

__device__ __forceinline__ uint32_t rp2(float a, float b, uint32_t nv)
{
    __nv_bfloat162 n = *reinterpret_cast<const __nv_bfloat162*>(&nv);
    float x0 = a + __bfloat162float(n.x);
    float x1 = b + __bfloat162float(n.y);
    __nv_bfloat162 o = __floats2bfloat162_rn(fmaxf(x0, 0.f), fmaxf(x1, 0.f));
    return *reinterpret_cast<uint32_t*>(&o);
}

__device__ __forceinline__ void cp16(uint32_t dst, const void* src)
{
    asm volatile("cp.async.cg.shared.global [%0], [%1], 16;" :: "r"(dst), "l"(src));
}
#define CP_COMMIT() asm volatile("cp.async.commit_group;" ::: "memory")
#define CP_WAIT0()  asm volatile("cp.async.wait_group 0;" ::: "memory")

__global__ __launch_bounds__(256, 1) void match_kernel(
    const float* __restrict__ W3, const float* __restrict__ b2v,
    const float* __restrict__ b3,
    const float* __restrict__ Wc1, const float* __restrict__ bc1,
    const float* __restrict__ Wc2, const float* __restrict__ bc2,
    float* __restrict__ out)
{
    extern __shared__ char sm[];
    float* sW3 = (float*)(sm + SM_W3);
    float* sb2 = (float*)(sm + SM_B2);
    float* zpart = (float*)(sm + SM_ZP);

    int tid = threadIdx.x;
    int lane = tid & 31, wid = tid >> 5;
    int wm = wid >> 1, wn = wid & 1;

    const int t1Off[2] = {SM_T1_0, SM_T1_1};
    const int n1Off[2] = {SM_N1_0, SM_N1_1};
    uint32_t smuBase = (uint32_t)__cvta_generic_to_shared(sm);

    // ---- coordination head on the last (53-tile) CTA, using SM_A scratch ----
    if (blockIdx.x == GRID_MATCH - 1) {
        float* ps = (float*)(sm + SM_A);       // 256
        float* gs = ps + 256;                  // 128
        float* hh = gs + 128;                  // 256
        int d = tid & 127, half = tid >> 7;
        float s = 0.f;
        for (int r = half * 512; r < half * 512 + 512; r++) s += g_att[r * 128 + d];
        ps[tid] = s;
        __syncthreads();
        if (tid < 128) gs[tid] = (ps[tid] + ps[tid + 128]) * (1.f / 1024.f);
        __syncthreads();
        float hv = bc1[tid];
        for (int c = 0; c < 128; c++) hv = fmaf(gs[c], Wc1[tid * 128 + c], hv);
        hh[tid] = fmaxf(hv, 0.f);
        __syncthreads();
        if (tid < 32) {
            float z = bc2[tid];
            for (int c = 0; c < 256; c++) z = fmaf(hh[c], Wc2[tid * 256 + c], z);
            out[1048576 + tid] = z;
        }
        __syncthreads();
    }

    // ---- one-time staging: W2, W3, b2 ----
    {
        const uint4* bsrc = (const uint4*)g_W2bf;
#pragma unroll
        for (int j = 0; j < 16; j++) {
            int i = tid + j * 256;
            int r = i >> 5, q = i & 31;
            *(uint4*)(sm + SM_B + r * ROWSTRIDE_B + q * 16) = bsrc[i];
        }
        if (tid < 128) { sW3[tid] = W3[tid]; sb2[tid] = b2v[tid]; }
    }
    float b3v = b3[0];

    uint32_t aSm = (uint32_t)__cvta_generic_to_shared(sm + SM_A);
    uint32_t bSm = (uint32_t)__cvta_generic_to_shared(sm + SM_B);

    uint32_t aBase[2];
#pragma unroll
    for (int mt = 0; mt < 2; mt++) {
        int row = wm * 32 + mt * 16 + (lane & 15);
        int colb = ((lane >> 4) << 3) * 2;
        aBase[mt] = aSm + row * ROWSTRIDE_B + colb;
    }
    uint32_t bBase[4];
#pragma unroll
    for (int nt2 = 0; nt2 < 4; nt2++) {
        int nrow = wn * 64 + nt2 * 16 + ((lane >> 4) << 3) + (lane & 7);
        int kb = (((lane >> 3) & 1) << 3) * 2;
        bBase[nt2] = bSm + nrow * ROWSTRIDE_B + kb;
    }
    __syncthreads();

    int firstTile = blockIdx.x;
    if (firstTile < NTILES) {
        int t0 = (firstTile >> 6) * 8, n0 = (firstTile & 63) * 16;
        const float4* ts = (const float4*)(g_t1 + (size_t)t0 * 256);
        const uint4* ns = (const uint4*)(g_n1bf + (size_t)n0 * 256);
        cp16(smuBase + SM_T1_0 + tid * 16, ts + tid);
        cp16(smuBase + SM_T1_0 + (tid + 256) * 16, ts + tid + 256);
        {
            int i0 = tid, i1 = tid + 256;
            cp16(smuBase + SM_N1_0 + (i0 >> 5) * N1STRIDE + (i0 & 31) * 16, ns + i0);
            cp16(smuBase + SM_N1_0 + (i1 >> 5) * N1STRIDE + (i1 & 31) * 16, ns + i1);
        }
        CP_COMMIT();
    }

    int bi = 0;
    for (int tile = firstTile; tile < NTILES; tile += GRID_MATCH, bi ^= 1) {
        int n0 = (tile & 63) * 16, t0 = (tile >> 6) * 8;

        CP_WAIT0();
        __syncthreads();

        {
            const float4* t1f4 = (const float4*)(sm + t1Off[bi]);
            const char* n1b = sm + n1Off[bi];
            int r = tid & 127, qp = tid >> 7;
            int tl = r >> 4, nl = r & 15;
            const char* n1row = n1b + nl * N1STRIDE;
            char* aRow = sm + SM_A + r * ROWSTRIDE_B;
            const float4* t1row = t1f4 + tl * 64;
#pragma unroll
            for (int j = 0; j < 16; j++) {
                int q = qp + 2 * j;
                float4 ta = t1row[q * 2];
                float4 tb = t1row[q * 2 + 1];
                uint4 nv = *(const uint4*)(n1row + q * 16);
                uint4 o;
                o.x = rp2(ta.x, ta.y, nv.x);
                o.y = rp2(ta.z, ta.w, nv.y);
                o.z = rp2(tb.x, tb.y, nv.z);
                o.w = rp2(tb.z, tb.w, nv.w);
                *(uint4*)(aRow + q * 16) = o;
            }
        }
        __syncthreads();

        int nextTile = tile + GRID_MATCH;
        if (nextTile < NTILES) {
            int nt0 = (nextTile >> 6) * 8, nn0 = (nextTile & 63) * 16;
            const float4* ts = (const float4*)(g_t1 + (size_t)nt0 * 256);
            const uint4* ns = (const uint4*)(g_n1bf + (size_t)nn0 * 256);
            int tb = t1Off[bi ^ 1], nb = n1Off[bi ^ 1];
            cp16(smuBase + tb + tid * 16, ts + tid);
            cp16(smuBase + tb + (tid + 256) * 16, ts + tid + 256);
            int i0 = tid, i1 = tid + 256;
            cp16(smuBase + nb + (i0 >> 5) * N1STRIDE + (i0 & 31) * 16, ns + i0);
            cp16(smuBase + nb + (i1 >> 5) * N1STRIDE + (i1 & 31) * 16, ns + i1);
        }
        CP_COMMIT();

        float c[2][8][4];
#pragma unroll
        for (int mt = 0; mt < 2; mt++)
#pragma unroll
            for (int nt = 0; nt < 8; nt++)
#pragma unroll
                for (int j = 0; j < 4; j++) c[mt][nt][j] = 0.f;

        uint32_t a[2][2][4];
        uint32_t b[2][8][2];
#pragma unroll
        for (int mt = 0; mt < 2; mt++)
            ldm_x4(a[0][mt][0], a[0][mt][1], a[0][mt][2], a[0][mt][3], aBase[mt]);
#pragma unroll
        for (int nt2 = 0; nt2 < 4; nt2++) {
            uint32_t r0, r1, r2, r3;
            ldm_x4(r0, r1, r2, r3, bBase[nt2]);
            b[0][2 * nt2][0] = r0; b[0][2 * nt2][1] = r1;
            b[0][2 * nt2 + 1][0] = r2; b[0][2 * nt2 + 1][1] = r3;
        }

#pragma unroll
        for (int kk = 0; kk < 16; kk++) {
            int cur = kk & 1, nxt = cur ^ 1;
            if (kk < 15) {
                int ko = (kk + 1) * 32;
#pragma unroll
                for (int mt = 0; mt < 2; mt++)
                    ldm_x4(a[nxt][mt][0], a[nxt][mt][1], a[nxt][mt][2], a[nxt][mt][3],
                           aBase[mt] + ko);
#pragma unroll
                for (int nt2 = 0; nt2 < 4; nt2++) {
                    uint32_t r0, r1, r2, r3;
                    ldm_x4(r0, r1, r2, r3, bBase[nt2] + ko);
                    b[nxt][2 * nt2][0] = r0; b[nxt][2 * nt2][1] = r1;
                    b[nxt][2 * nt2 + 1][0] = r2; b[nxt][2 * nt2 + 1][1] = r3;
                }
            }
#pragma unroll
            for (int mt = 0; mt < 2; mt++)
#pragma unroll
                for (int nt = 0; nt < 8; nt++)
                    mma_bf16(c[mt][nt][0], c[mt][nt][1], c[mt][nt][2], c[mt][nt][3],
                             a[cur][mt][0], a[cur][mt][1], a[cur][mt][2], a[cur][mt][3],
                             b[cur][nt][0], b[cur][nt][1]);
        }

        int g = lane >> 2, q = lane & 3;
#pragma unroll
        for (int mt = 0; mt < 2; mt++) {
            float p0 = 0.f, p1 = 0.f;
#pragma unroll
            for (int nt = 0; nt < 8; nt++) {
                int col = wn * 64 + nt * 8 + q * 2;
                float w0 = sW3[col], w1 = sW3[col + 1];
                float bb0 = sb2[col], bb1 = sb2[col + 1];
                p0 += fmaxf(c[mt][nt][0] + bb0, 0.f) * w0 + fmaxf(c[mt][nt][1] + bb1, 0.f) * w1;
                p1 += fmaxf(c[mt][nt][2] + bb0, 0.f) * w0 + fmaxf(c[mt][nt][3] + bb1, 0.f) * w1;
            }
            p0 += __shfl_xor_sync(0xffffffffu, p0, 1);
            p0 += __shfl_xor_sync(0xffffffffu, p0, 2);
            p1 += __shfl_xor_sync(0xffffffffu, p1, 1);
            p1 += __shfl_xor_sync(0xffffffffu, p1, 2);
            if (q == 0) {
                int rA = wm * 32 + mt * 16 + g;
                zpart[rA * 2 + wn] = p0;
                zpart[(rA + 8) * 2 + wn] = p1;
            }
        }
        __syncthreads();
        if (tid < 128) {
            float z = zpart[tid * 2] + zpart[tid * 2 + 1] + b3v;
            float s = 1.f / (1.f + expf(-z));
            int t = t0 + (tid >> 4), n = n0 + (tid & 15);
            out[(size_t)t * 1024 + n] = s;
        }
        __syncthreads();
    }
}

// ---------------- launch ---------------------------------------------------
extern "C" void kernel_launch(void* const* d_in, const int* in_sizes, int n_in,
                              void* d_out, int out_size)
{
    const float* node = (const float*)d_in[0];
    const float* task = (const float*)d_in[1];
    const float* ipw  = (const float*)d_in[2];
    const float* ipb  = (const float*)d_in[3];
    const float* outw = (const float*)d_in[4];
    const float* outb = (const float*)d_in[5];
    const float* W1   = (const float*)d_in[6];
    const float* b1   = (const float*)d_in[7];
    const float* W2   = (const float*)d_in[8];
    const float* b2   = (const float*)d_in[9];
    const float* W3   = (const float*)d_in[10];
    const float* b3   = (const float*)d_in[11];
    const float* Wc1  = (const float*)d_in[12];
    const float* bc1  = (const float*)d_in[13];
    const float* Wc2  = (const float*)d_in[14];
    const float* bc2  = (const float*)d_in[15];
    float* out = (float*)d_out;

    float *qkv, *scores;
    cudaGetSymbolAddress((void**)&qkv, g_qkv);
    cudaGetSymbolAddress((void**)&scores, g_scores);

    // 0: QKV + t1 fused
    qkv_t1_kernel<<<dim3(6, 16, 2), 256>>>(node, ipw, ipb, task, W1, b1);
    // 1: scores (all 4 heads)
    gemm_f32b<<<dim3(16, 16, 4), 256>>>(qkv, 384, 32, qkv + 128, 384, 32,
                                        0.17677669529663687f, scores, 1024, 1048576, 32);
    // 2: softmax + head-mean + W2->bf16
    softmax_fused<<<1024, 256>>>(W2, out + 1048608);
    // 3: ctx partials (deterministic split-K x8 for occupancy)
    cudaFuncSetAttribute(ctx_kernel, cudaFuncAttributeMaxDynamicSharedMemorySize, 50688);
    ctx_kernel<<<dim3(8, 16, 4), 256, 50688>>>();
    // 4: attended projection (sums partials) + n1 (bf16) fused
    att_n1<<<dim3(4, 16), 256>>>(outw, outb, W1);
    // 5: persistent bf16 HMMA pairwise MLP + coordination head (CTA 151)
    cudaFuncSetAttribute(match_kernel, cudaFuncAttributeMaxDynamicSharedMemorySize, SMEM_TOTAL);
    match_kernel<<<GRID_MATCH, 256, SMEM_TOTAL>>>(W3, b2, b3, Wc1, bc1, Wc2, bc2, out);
}